// round 1
// baseline (speedup 1.0000x reference)
#include <cuda_runtime.h>
#include <cstdint>
#include <cstddef>

// Problem constants
#define Bdim 2
#define Tdim 4096
#define Cdim 1024
#define Hdim 16
#define Ddim 64
#define MROWS (Bdim*Tdim)   // 8192

// ---------------- scratch (static device globals; no allocation) ----------
__device__ float g_qkv[MROWS * 3 * Cdim];   // [8192, 3072]
__device__ float g_q[MROWS * Cdim];         // [B,T,H,D] flattened
__device__ float g_k[MROWS * Cdim];
__device__ float g_v[MROWS * Cdim];
__device__ float g_o1[MROWS * Cdim];
__device__ float g_o2[MROWS * Cdim];
__device__ float g_o3[MROWS * Cdim];
__device__ float g_l1[MROWS * Hdim];
__device__ float g_l2[MROWS * Hdim];
__device__ float g_l3[MROWS * Hdim];
__device__ float g_y[MROWS * Cdim];

// ---------------- SGEMM: C = alpha * (A @ B + bias) -----------------------
// A: [M, K] row-major with stride lda; B: [K, N] row-major stride ldb.
// 128x128 block tile, K-step 16, 256 threads, 8x8 register tile.
__global__ __launch_bounds__(256) void sgemm_bias(
    const float* __restrict__ A, int lda,
    const float* __restrict__ Bw, int ldb,
    const float* __restrict__ bias,
    float* __restrict__ Cm, int ldc,
    int M, int N, int K, float alpha)
{
    __shared__ float As[16][128];   // transposed: As[k][m]
    __shared__ float Bs[16][128];   // Bs[k][n]

    const int tid = threadIdx.x;
    const int tx = tid & 15;        // 0..15 (column groups)
    const int ty = tid >> 4;        // 0..15 (row groups)
    const int m0 = blockIdx.y * 128;
    const int n0 = blockIdx.x * 128;

    float acc[8][8];
#pragma unroll
    for (int i = 0; i < 8; i++)
#pragma unroll
        for (int j = 0; j < 8; j++) acc[i][j] = 0.f;

    for (int k0 = 0; k0 < K; k0 += 16) {
        // Load A tile [128 rows x 16 k] -> transposed smem
#pragma unroll
        for (int t = 0; t < 2; t++) {
            int li = tid + t * 256;          // 0..511 float4s
            int row = li >> 2;               // 0..127
            int k4 = li & 3;                 // 0..3
            const float4 v = *(const float4*)(A + (size_t)(m0 + row) * lda + k0 + k4 * 4);
            As[k4 * 4 + 0][row] = v.x;
            As[k4 * 4 + 1][row] = v.y;
            As[k4 * 4 + 2][row] = v.z;
            As[k4 * 4 + 3][row] = v.w;
        }
        // Load B tile [16 k x 128 n]
#pragma unroll
        for (int t = 0; t < 2; t++) {
            int li = tid + t * 256;
            int kk = li >> 5;                // 0..15
            int n4 = li & 31;                // 0..31
            const float4 v = *(const float4*)(Bw + (size_t)(k0 + kk) * ldb + n0 + n4 * 4);
            *(float4*)&Bs[kk][n4 * 4] = v;
        }
        __syncthreads();

#pragma unroll
        for (int kk = 0; kk < 16; kk++) {
            float a[8], b[8];
            *(float4*)&a[0] = *(float4*)&As[kk][ty * 8];
            *(float4*)&a[4] = *(float4*)&As[kk][ty * 8 + 4];
            *(float4*)&b[0] = *(float4*)&Bs[kk][tx * 8];
            *(float4*)&b[4] = *(float4*)&Bs[kk][tx * 8 + 4];
#pragma unroll
            for (int i = 0; i < 8; i++)
#pragma unroll
                for (int j = 0; j < 8; j++)
                    acc[i][j] = fmaf(a[i], b[j], acc[i][j]);
        }
        __syncthreads();
    }

    float bv[8];
#pragma unroll
    for (int j = 0; j < 8; j++) bv[j] = bias[n0 + tx * 8 + j];

#pragma unroll
    for (int i = 0; i < 8; i++) {
        float out[8];
#pragma unroll
        for (int j = 0; j < 8; j++) out[j] = alpha * (acc[i][j] + bv[j]);
        float* dst = Cm + (size_t)(m0 + ty * 8 + i) * ldc + n0 + tx * 8;
        *(float4*)&dst[0] = *(float4*)&out[0];
        *(float4*)&dst[4] = *(float4*)&out[4];
    }
}

// ---------------- dilated attention branch (flash-style) ------------------
// eff = W/R = 512 for all branches. One block = (b, h, seg, 128-query tile).
// Gathered index gi maps to position t = seg*W + (h%R) + gi*R.
// Smem: Qs[128][65], Ks[64][65], Vs[64][65], Ps[128][65]  (~97.5 KB)
#define ATTN_SMEM (384 * 65 * 4)

__global__ __launch_bounds__(256) void attn_branch(
    const float* __restrict__ Qm, const float* __restrict__ Km,
    const float* __restrict__ Vm, float* __restrict__ Obuf,
    float* __restrict__ Lbuf, int W, int R)
{
    extern __shared__ float sm[];
    float* Qs = sm;                  // [128][65]
    float* Ks = Qs + 128 * 65;       // [64][65]
    float* Vs = Ks + 64 * 65;        // [64][65]
    float* Ps = Vs + 64 * 65;        // [128][65]

    const int b   = blockIdx.z;
    const int h   = blockIdx.y;
    const int seg = blockIdx.x >> 2;
    const int qt  = blockIdx.x & 3;
    const int tid = threadIdx.x;
    const int cx  = tid & 7;         // column group (8 cols each)
    const int ry  = tid >> 3;        // row group (4 rows each)
    const int segbase = seg * W + (h & (R - 1));
    const int qBase = qt * 128;

    // Load Q tile [128, 64]
#pragma unroll
    for (int t = 0; t < 8; t++) {
        int li = tid + t * 256;              // 0..2047 float4s
        int i  = li >> 4;                    // row 0..127
        int d4 = li & 15;
        int tp = segbase + (qBase + i) * R;
        const float4 v = *(const float4*)(Qm + ((size_t)(b * Tdim + tp) * Cdim) + h * Ddim + d4 * 4);
        float* dst = Qs + i * 65 + d4 * 4;
        dst[0] = v.x; dst[1] = v.y; dst[2] = v.z; dst[3] = v.w;
    }

    float m_r[4], l_r[4], oacc[4][8];
#pragma unroll
    for (int i = 0; i < 4; i++) {
        m_r[i] = -1e30f; l_r[i] = 0.f;
#pragma unroll
        for (int j = 0; j < 8; j++) oacc[i][j] = 0.f;
    }

    const int ntiles = qt * 2 + 2;           // causal bound
    for (int jt = 0; jt < ntiles; jt++) {
        const int j0 = jt * 64;
        __syncthreads();
        // Load K,V tiles [64, 64]
#pragma unroll
        for (int t = 0; t < 4; t++) {
            int li = tid + t * 256;          // 0..1023 float4s
            int j  = li >> 4;                // key 0..63
            int d4 = li & 15;
            int tp = segbase + (j0 + j) * R;
            size_t g = ((size_t)(b * Tdim + tp) * Cdim) + h * Ddim + d4 * 4;
            const float4 kv = *(const float4*)(Km + g);
            const float4 vv = *(const float4*)(Vm + g);
            float* kd = Ks + j * 65 + d4 * 4;
            kd[0] = kv.x; kd[1] = kv.y; kd[2] = kv.z; kd[3] = kv.w;
            float* vd = Vs + j * 65 + d4 * 4;
            vd[0] = vv.x; vd[1] = vv.y; vd[2] = vv.z; vd[3] = vv.w;
        }
        __syncthreads();

        // S = Q K^T   (thread owns rows ry*4..+3, cols cx*8..+7)
        float s[4][8];
#pragma unroll
        for (int i = 0; i < 4; i++)
#pragma unroll
            for (int j = 0; j < 8; j++) s[i][j] = 0.f;

#pragma unroll 8
        for (int d = 0; d < 64; d++) {
            float a[4], bb[8];
#pragma unroll
            for (int i = 0; i < 4; i++) a[i] = Qs[(ry * 4 + i) * 65 + d];
#pragma unroll
            for (int j = 0; j < 8; j++) bb[j] = Ks[(cx * 8 + j) * 65 + d];
#pragma unroll
            for (int i = 0; i < 4; i++)
#pragma unroll
                for (int j = 0; j < 8; j++)
                    s[i][j] = fmaf(a[i], bb[j], s[i][j]);
        }

        // Causal mask on diagonal tiles
        if (j0 + 64 > qBase) {
#pragma unroll
            for (int i = 0; i < 4; i++) {
                int qg = qBase + ry * 4 + i;
#pragma unroll
                for (int j = 0; j < 8; j++)
                    if (j0 + cx * 8 + j > qg) s[i][j] = -1e30f;
            }
        }

        // Online softmax per row (8 lanes share a row -> shfl-xor over 1,2,4)
#pragma unroll
        for (int i = 0; i < 4; i++) {
            float rm = s[i][0];
#pragma unroll
            for (int j = 1; j < 8; j++) rm = fmaxf(rm, s[i][j]);
            rm = fmaxf(rm, __shfl_xor_sync(0xffffffffu, rm, 1));
            rm = fmaxf(rm, __shfl_xor_sync(0xffffffffu, rm, 2));
            rm = fmaxf(rm, __shfl_xor_sync(0xffffffffu, rm, 4));
            float mn = fmaxf(m_r[i], rm);
            float scale = __expf(m_r[i] - mn);
            float rs = 0.f;
#pragma unroll
            for (int j = 0; j < 8; j++) {
                float p = __expf(s[i][j] - mn);
                Ps[(ry * 4 + i) * 65 + cx * 8 + j] = p;
                rs += p;
            }
            rs += __shfl_xor_sync(0xffffffffu, rs, 1);
            rs += __shfl_xor_sync(0xffffffffu, rs, 2);
            rs += __shfl_xor_sync(0xffffffffu, rs, 4);
            l_r[i] = l_r[i] * scale + rs;
            m_r[i] = mn;
#pragma unroll
            for (int j = 0; j < 8; j++) oacc[i][j] *= scale;
        }
        // Ps rows are written and read by the same warp -> warp sync suffices
        __syncwarp();

        // O += P V
#pragma unroll 8
        for (int kk = 0; kk < 64; kk++) {
            float a[4], bb[8];
#pragma unroll
            for (int i = 0; i < 4; i++) a[i] = Ps[(ry * 4 + i) * 65 + kk];
#pragma unroll
            for (int j = 0; j < 8; j++) bb[j] = Vs[kk * 65 + cx * 8 + j];
#pragma unroll
            for (int i = 0; i < 4; i++)
#pragma unroll
                for (int j = 0; j < 8; j++)
                    oacc[i][j] = fmaf(a[i], bb[j], oacc[i][j]);
        }
    }

    // Epilogue: normalize, scatter to true positions, write lse
#pragma unroll
    for (int i = 0; i < 4; i++) {
        float inv = 1.f / l_r[i];
        int gi = qBase + ry * 4 + i;
        int tp = segbase + gi * R;
        size_t obase = ((size_t)(b * Tdim + tp) * Cdim) + h * Ddim + cx * 8;
#pragma unroll
        for (int j = 0; j < 8; j++) Obuf[obase + j] = oacc[i][j] * inv;
        if (cx == 0)
            Lbuf[(size_t)(b * Tdim + tp) * Hdim + h] = m_r[i] + __logf(l_r[i]);
    }
}

// ---------------- combine branches (lse-weighted) --------------------------
__global__ __launch_bounds__(256) void combine_kernel(
    const float* __restrict__ O1, const float* __restrict__ O2,
    const float* __restrict__ O3, const float* __restrict__ L1,
    const float* __restrict__ L2, const float* __restrict__ L3,
    float* __restrict__ Y)
{
    int idx = blockIdx.x * 256 + threadIdx.x;   // over B*T*C
    int c = idx & (Cdim - 1);
    int bt = idx >> 10;                          // b*T + t
    int t = bt & (Tdim - 1);
    int h = c >> 6;
    int li = bt * Hdim + h;

    float l1 = L1[li];
    bool p2 = (((t ^ h) & 1) == 0);
    bool p3 = (((t ^ h) & 3) == 0);
    float l2 = p2 ? L2[li] : -1e30f;
    float l3 = p3 ? L3[li] : -1e30f;
    float m = fmaxf(l1, fmaxf(l2, l3));
    float w1 = __expf(l1 - m);
    float w2 = p2 ? __expf(l2 - m) : 0.f;
    float w3 = p3 ? __expf(l3 - m) : 0.f;
    float num = w1 * O1[idx];
    if (p2) num += w2 * O2[idx];
    if (p3) num += w3 * O3[idx];
    Y[idx] = num / (w1 + w2 + w3);
}

// ---------------- launcher --------------------------------------------------
extern "C" void kernel_launch(void* const* d_in, const int* in_sizes, int n_in,
                              void* d_out, int out_size)
{
    const float* x        = (const float*)d_in[0];
    const float* c_attn_w = (const float*)d_in[1];
    const float* c_attn_b = (const float*)d_in[2];
    const float* q_w      = (const float*)d_in[3];
    const float* q_b      = (const float*)d_in[4];
    const float* k_w      = (const float*)d_in[5];
    const float* k_b      = (const float*)d_in[6];
    const float* v_w      = (const float*)d_in[7];
    const float* v_b      = (const float*)d_in[8];
    const float* o_w      = (const float*)d_in[9];
    const float* o_b      = (const float*)d_in[10];
    float* out = (float*)d_out;

    float *p_qkv, *p_q, *p_k, *p_v, *p_o1, *p_o2, *p_o3, *p_l1, *p_l2, *p_l3, *p_y;
    cudaGetSymbolAddress((void**)&p_qkv, g_qkv);
    cudaGetSymbolAddress((void**)&p_q, g_q);
    cudaGetSymbolAddress((void**)&p_k, g_k);
    cudaGetSymbolAddress((void**)&p_v, g_v);
    cudaGetSymbolAddress((void**)&p_o1, g_o1);
    cudaGetSymbolAddress((void**)&p_o2, g_o2);
    cudaGetSymbolAddress((void**)&p_o3, g_o3);
    cudaGetSymbolAddress((void**)&p_l1, g_l1);
    cudaGetSymbolAddress((void**)&p_l2, g_l2);
    cudaGetSymbolAddress((void**)&p_l3, g_l3);
    cudaGetSymbolAddress((void**)&p_y, g_y);

    cudaFuncSetAttribute(attn_branch, cudaFuncAttributeMaxDynamicSharedMemorySize, ATTN_SMEM);

    const float qscale = 0.125f;  // D^-0.5, D=64

    // 1) qkv = x @ c_attn_w + c_attn_b              [8192, 3072]
    sgemm_bias<<<dim3(3072 / 128, MROWS / 128), 256>>>(
        x, Cdim, c_attn_w, 3 * Cdim, c_attn_b, p_qkv, 3 * Cdim,
        MROWS, 3 * Cdim, Cdim, 1.f);

    // 2) q/k/v projections (q scaled by D^-0.5)
    sgemm_bias<<<dim3(Cdim / 128, MROWS / 128), 256>>>(
        p_qkv + 0 * Cdim, 3 * Cdim, q_w, Cdim, q_b, p_q, Cdim,
        MROWS, Cdim, Cdim, qscale);
    sgemm_bias<<<dim3(Cdim / 128, MROWS / 128), 256>>>(
        p_qkv + 1 * Cdim, 3 * Cdim, k_w, Cdim, k_b, p_k, Cdim,
        MROWS, Cdim, Cdim, 1.f);
    sgemm_bias<<<dim3(Cdim / 128, MROWS / 128), 256>>>(
        p_qkv + 2 * Cdim, 3 * Cdim, v_w, Cdim, v_b, p_v, Cdim,
        MROWS, Cdim, Cdim, 1.f);

    // 3) three dilated-attention branches (eff=512 each, 4 q-tiles per unit)
    attn_branch<<<dim3(8 * 4, Hdim, Bdim), 256, ATTN_SMEM>>>(
        p_q, p_k, p_v, p_o1, p_l1, 512, 1);
    attn_branch<<<dim3(4 * 4, Hdim, Bdim), 256, ATTN_SMEM>>>(
        p_q, p_k, p_v, p_o2, p_l2, 1024, 2);
    attn_branch<<<dim3(2 * 4, Hdim, Bdim), 256, ATTN_SMEM>>>(
        p_q, p_k, p_v, p_o3, p_l3, 2048, 4);

    // 4) lse-weighted combine -> y [B,T,C]
    combine_kernel<<<(MROWS * Cdim) / 256, 256>>>(
        p_o1, p_o2, p_o3, p_l1, p_l2, p_l3, p_y);

    // 5) out = y @ o_w + o_b
    sgemm_bias<<<dim3(Cdim / 128, MROWS / 128), 256>>>(
        p_y, Cdim, o_w, Cdim, o_b, out, Cdim,
        MROWS, Cdim, Cdim, 1.f);
}

// round 3
// speedup vs baseline: 1.9713x; 1.9713x over previous
#include <cuda_runtime.h>
#include <cuda_bf16.h>
#include <cstdint>
#include <cstddef>

// Problem constants
#define Bdim 2
#define Tdim 4096
#define Cdim 1024
#define Hdim 16
#define Ddim 64
#define MROWS (Bdim*Tdim)   // 8192

// ====================== helpers ============================================
__device__ __forceinline__ uint32_t smem_to_u32(const void* p) {
    uint32_t addr;
    asm("{ .reg .u64 tmp; cvta.to.shared.u64 tmp, %1; cvt.u32.u64 %0, tmp; }"
        : "=r"(addr) : "l"(p));
    return addr;
}
#define SWZ(x) ((x) ^ (((x) >> 3) & 0x70))

__device__ __forceinline__ void cpa16(uint32_t s, const void* g) {
    asm volatile("cp.async.cg.shared.global [%0], [%1], 16;" :: "r"(s), "l"(g));
}
#define CPA_COMMIT() asm volatile("cp.async.commit_group;")
#define CPA_WAIT0()  asm volatile("cp.async.wait_group 0;")

__device__ __forceinline__ void ldm_x4(uint32_t* r, uint32_t addr) {
    asm volatile("ldmatrix.sync.aligned.m8n8.x4.shared.b16 {%0,%1,%2,%3}, [%4];"
        : "=r"(r[0]), "=r"(r[1]), "=r"(r[2]), "=r"(r[3]) : "r"(addr));
}
__device__ __forceinline__ void mma16816(float* d, const uint32_t* a, const uint32_t* b) {
    asm volatile(
        "mma.sync.aligned.m16n8k16.row.col.f32.bf16.bf16.f32 "
        "{%0,%1,%2,%3}, {%4,%5,%6,%7}, {%8,%9}, {%0,%1,%2,%3};"
        : "+f"(d[0]), "+f"(d[1]), "+f"(d[2]), "+f"(d[3])
        : "r"(a[0]), "r"(a[1]), "r"(a[2]), "r"(a[3]), "r"(b[0]), "r"(b[1]));
}

// ====================== scratch (static device globals) ====================
__device__ __nv_bfloat16 g_xhi[MROWS * Cdim];
__device__ __nv_bfloat16 g_xlo[MROWS * Cdim];
__device__ __nv_bfloat16 g_cawh[3 * Cdim * Cdim];   // c_attn_w^T [3072][1024]
__device__ __nv_bfloat16 g_cawl[3 * Cdim * Cdim];
__device__ __nv_bfloat16 g_qwh[Cdim * Cdim];
__device__ __nv_bfloat16 g_qwl[Cdim * Cdim];
__device__ __nv_bfloat16 g_kwh[Cdim * Cdim];
__device__ __nv_bfloat16 g_kwl[Cdim * Cdim];
__device__ __nv_bfloat16 g_vwh[Cdim * Cdim];
__device__ __nv_bfloat16 g_vwl[Cdim * Cdim];
__device__ __nv_bfloat16 g_owh[Cdim * Cdim];
__device__ __nv_bfloat16 g_owl[Cdim * Cdim];
__device__ __nv_bfloat16 g_qkvh[MROWS * 3 * Cdim];
__device__ __nv_bfloat16 g_qkvl[MROWS * 3 * Cdim];
__device__ __nv_bfloat16 g_yh[MROWS * Cdim];
__device__ __nv_bfloat16 g_yl[MROWS * Cdim];
__device__ float g_q[MROWS * Cdim];
__device__ float g_k[MROWS * Cdim];
__device__ float g_v[MROWS * Cdim];
__device__ float g_o1[MROWS * Cdim];
__device__ float g_o2[MROWS * Cdim];
__device__ float g_o3[MROWS * Cdim];
__device__ float g_l1[MROWS * Hdim];
__device__ float g_l2[MROWS * Hdim];
__device__ float g_l3[MROWS * Hdim];

// ====================== conversion kernels =================================
__global__ __launch_bounds__(256) void split_kernel(
    const float* __restrict__ in, __nv_bfloat16* __restrict__ hi,
    __nv_bfloat16* __restrict__ lo, int n)
{
    int i = (blockIdx.x * 256 + threadIdx.x) * 4;
    if (i >= n) return;
    float4 v = *(const float4*)(in + i);
    float vv[4] = {v.x, v.y, v.z, v.w};
    __nv_bfloat16 h[4], l[4];
#pragma unroll
    for (int k = 0; k < 4; k++) {
        h[k] = __float2bfloat16(vv[k]);
        l[k] = __float2bfloat16(vv[k] - __bfloat162float(h[k]));
    }
    *(uint2*)(hi + i) = *(uint2*)h;
    *(uint2*)(lo + i) = *(uint2*)l;
}

// W [K][N] fp32 -> Wt_hi/lo [N][K] bf16
__global__ __launch_bounds__(256) void transpose_split(
    const float* __restrict__ W, int K, int N,
    __nv_bfloat16* __restrict__ Th, __nv_bfloat16* __restrict__ Tl)
{
    __shared__ float tile[32][33];
    int n0 = blockIdx.x * 32, k0 = blockIdx.y * 32;
    int tx = threadIdx.x, ty = threadIdx.y;   // (32, 8)
#pragma unroll
    for (int r = 0; r < 4; r++)
        tile[ty + r * 8][tx] = W[(size_t)(k0 + ty + r * 8) * N + n0 + tx];
    __syncthreads();
#pragma unroll
    for (int r = 0; r < 4; r++) {
        float v = tile[tx][ty + r * 8];
        __nv_bfloat16 h = __float2bfloat16(v);
        size_t o = (size_t)(n0 + ty + r * 8) * K + k0 + tx;
        Th[o] = h;
        Tl[o] = __float2bfloat16(v - __bfloat162float(h));
    }
}

// ====================== HMMA bf16x3 GEMM ===================================
// C[M,N] = alpha * (A @ B^T + bias);  A[M,K] hi/lo bf16, B[N,K] hi/lo bf16.
// CTA 128x128, 8 warps (2x4), warp tile 64x32, BK=64, cp.async double buffer.
#define HG_STAGE 65536
#define HG_SMEM  (2 * HG_STAGE)

__device__ __forceinline__ void hg_load_stage(
    uint32_t sbase, int buf,
    const __nv_bfloat16* __restrict__ a_hi, const __nv_bfloat16* __restrict__ a_lo,
    size_t m0, int lda,
    const __nv_bfloat16* __restrict__ b_hi, const __nv_bfloat16* __restrict__ b_lo,
    size_t n0, int ldb, int k0, int tid)
{
    uint32_t sAh = sbase + buf * HG_STAGE;
    uint32_t sAl = sAh + 16384;
    uint32_t sBh = sAh + 32768;
    uint32_t sBl = sAh + 49152;
#pragma unroll
    for (int t = 0; t < 4; t++) {
        int i = tid + t * 256;          // 0..1023
        int row = i >> 3, u = i & 7;    // row 0..127, u 16B-chunk 0..7
        uint32_t soff = SWZ(row * 128 + u * 16);
        size_t ga = (m0 + row) * (size_t)lda + k0 + u * 8;
        size_t gb = (n0 + row) * (size_t)ldb + k0 + u * 8;
        cpa16(sAh + soff, a_hi + ga);
        cpa16(sAl + soff, a_lo + ga);
        cpa16(sBh + soff, b_hi + gb);
        cpa16(sBl + soff, b_lo + gb);
    }
}

__global__ __launch_bounds__(256, 1) void hmma_gemm(
    const __nv_bfloat16* __restrict__ a_hi, const __nv_bfloat16* __restrict__ a_lo, int lda,
    const __nv_bfloat16* __restrict__ b_hi, const __nv_bfloat16* __restrict__ b_lo, int ldb,
    const float* __restrict__ bias,
    float* __restrict__ outf,
    __nv_bfloat16* __restrict__ out_hi, __nv_bfloat16* __restrict__ out_lo,
    int ldc, int K, float alpha, int mode)
{
    extern __shared__ char sm[];
    const uint32_t sbase = smem_to_u32(sm);
    const int tid  = threadIdx.x;
    const int warp = tid >> 5, lane = tid & 31;
    const int wm0 = (warp >> 2) * 64;    // 0 or 64
    const int wn0 = (warp & 3) * 32;     // 0,32,64,96
    const size_t m0 = (size_t)blockIdx.y * 128;
    const size_t n0 = (size_t)blockIdx.x * 128;
    const int NC = K >> 6;               // 64-elem K chunks

    float acc[4][4][4];
#pragma unroll
    for (int i = 0; i < 4; i++)
#pragma unroll
        for (int j = 0; j < 4; j++)
#pragma unroll
            for (int r = 0; r < 4; r++) acc[i][j][r] = 0.f;

    hg_load_stage(sbase, 0, a_hi, a_lo, m0, lda, b_hi, b_lo, n0, ldb, 0, tid);
    CPA_COMMIT();

    const int g = lane >> 3;           // ldmatrix address group
    const int l7 = lane & 7;

    for (int c = 0; c < NC; ++c) {
        CPA_WAIT0();
        __syncthreads();
        if (c + 1 < NC) {
            hg_load_stage(sbase, (c + 1) & 1, a_hi, a_lo, m0, lda,
                          b_hi, b_lo, n0, ldb, (c + 1) * 64, tid);
            CPA_COMMIT();
        }
        uint32_t sAh = sbase + (c & 1) * HG_STAGE;
        uint32_t sAl = sAh + 16384;
        uint32_t sBh = sAh + 32768;
        uint32_t sBl = sAh + 49152;

#pragma unroll
        for (int ks = 0; ks < 4; ks++) {
            // A fragments: 4 m16 tiles, x4 ldmatrix each (hi & lo)
            uint32_t ah[4][4], al[4][4];
            {
                int arow = wm0 + (g & 1) * 8 + l7;
                int akb  = ks * 32 + ((g >> 1) & 1) * 16;
#pragma unroll
                for (int mt = 0; mt < 4; mt++) {
                    uint32_t off = SWZ((arow + mt * 16) * 128 + akb);
                    ldm_x4(ah[mt], sAh + off);
                    ldm_x4(al[mt], sAl + off);
                }
            }
            // B fragments: 4 n8 tiles (two x4 loads cover n16 each)
            uint32_t bh[4][2], bl[4][2];
            {
                int nrow = wn0 + ((g >> 1) & 1) * 8 + l7;
                int bkb  = ks * 32 + (g & 1) * 16;
#pragma unroll
                for (int nt = 0; nt < 2; nt++) {
                    uint32_t off = SWZ((nrow + nt * 16) * 128 + bkb);
                    uint32_t r[4];
                    ldm_x4(r, sBh + off);
                    bh[nt * 2 + 0][0] = r[0]; bh[nt * 2 + 0][1] = r[1];
                    bh[nt * 2 + 1][0] = r[2]; bh[nt * 2 + 1][1] = r[3];
                    ldm_x4(r, sBl + off);
                    bl[nt * 2 + 0][0] = r[0]; bl[nt * 2 + 0][1] = r[1];
                    bl[nt * 2 + 1][0] = r[2]; bl[nt * 2 + 1][1] = r[3];
                }
            }
#pragma unroll
            for (int mt = 0; mt < 4; mt++)
#pragma unroll
                for (int j = 0; j < 4; j++) {
                    mma16816(acc[mt][j], ah[mt], bh[j]);
                    mma16816(acc[mt][j], ah[mt], bl[j]);
                    mma16816(acc[mt][j], al[mt], bh[j]);
                }
        }
        __syncthreads();
    }

    // ---- epilogue ----
    const int qrow = lane >> 2;          // 0..7
    const int qcol = (lane & 3) * 2;     // 0,2,4,6
#pragma unroll
    for (int j = 0; j < 4; j++) {
        size_t col = n0 + wn0 + j * 8 + qcol;
        float b0 = bias[col], b1 = bias[col + 1];
#pragma unroll
        for (int mt = 0; mt < 4; mt++) {
            size_t row0 = m0 + wm0 + mt * 16 + qrow;
            size_t row1 = row0 + 8;
            float v00 = alpha * (acc[mt][j][0] + b0);
            float v01 = alpha * (acc[mt][j][1] + b1);
            float v10 = alpha * (acc[mt][j][2] + b0);
            float v11 = alpha * (acc[mt][j][3] + b1);
            if (mode == 0) {
                float2 r0 = {v00, v01}, r1 = {v10, v11};
                *(float2*)(outf + row0 * ldc + col) = r0;
                *(float2*)(outf + row1 * ldc + col) = r1;
            } else {
                __nv_bfloat162 hh0, ll0, hh1, ll1;
                hh0.x = __float2bfloat16(v00); hh0.y = __float2bfloat16(v01);
                ll0.x = __float2bfloat16(v00 - __bfloat162float(hh0.x));
                ll0.y = __float2bfloat16(v01 - __bfloat162float(hh0.y));
                hh1.x = __float2bfloat16(v10); hh1.y = __float2bfloat16(v11);
                ll1.x = __float2bfloat16(v10 - __bfloat162float(hh1.x));
                ll1.y = __float2bfloat16(v11 - __bfloat162float(hh1.y));
                *(uint32_t*)((char*)out_hi + (row0 * ldc + col) * 2) = *(uint32_t*)&hh0;
                *(uint32_t*)((char*)out_lo + (row0 * ldc + col) * 2) = *(uint32_t*)&ll0;
                *(uint32_t*)((char*)out_hi + (row1 * ldc + col) * 2) = *(uint32_t*)&hh1;
                *(uint32_t*)((char*)out_lo + (row1 * ldc + col) * 2) = *(uint32_t*)&ll1;
            }
        }
    }
}

// ---------------- dilated attention branch (flash-style, fp32) ------------
#define ATTN_SMEM (384 * 65 * 4)

__global__ __launch_bounds__(256) void attn_branch(
    const float* __restrict__ Qm, const float* __restrict__ Km,
    const float* __restrict__ Vm, float* __restrict__ Obuf,
    float* __restrict__ Lbuf, int W, int R)
{
    extern __shared__ float smf[];
    float* Qs = smf;
    float* Ks = Qs + 128 * 65;
    float* Vs = Ks + 64 * 65;
    float* Ps = Vs + 64 * 65;

    const int b   = blockIdx.z;
    const int h   = blockIdx.y;
    const int seg = blockIdx.x >> 2;
    const int qt  = blockIdx.x & 3;
    const int tid = threadIdx.x;
    const int cx  = tid & 7;
    const int ry  = tid >> 3;
    const int segbase = seg * W + (h & (R - 1));
    const int qBase = qt * 128;

#pragma unroll
    for (int t = 0; t < 8; t++) {
        int li = tid + t * 256;
        int i  = li >> 4;
        int d4 = li & 15;
        int tp = segbase + (qBase + i) * R;
        const float4 v = *(const float4*)(Qm + ((size_t)(b * Tdim + tp) * Cdim) + h * Ddim + d4 * 4);
        float* dst = Qs + i * 65 + d4 * 4;
        dst[0] = v.x; dst[1] = v.y; dst[2] = v.z; dst[3] = v.w;
    }

    float m_r[4], l_r[4], oacc[4][8];
#pragma unroll
    for (int i = 0; i < 4; i++) {
        m_r[i] = -1e30f; l_r[i] = 0.f;
#pragma unroll
        for (int j = 0; j < 8; j++) oacc[i][j] = 0.f;
    }

    const int ntiles = qt * 2 + 2;
    for (int jt = 0; jt < ntiles; jt++) {
        const int j0 = jt * 64;
        __syncthreads();
#pragma unroll
        for (int t = 0; t < 4; t++) {
            int li = tid + t * 256;
            int j  = li >> 4;
            int d4 = li & 15;
            int tp = segbase + (j0 + j) * R;
            size_t gidx = ((size_t)(b * Tdim + tp) * Cdim) + h * Ddim + d4 * 4;
            const float4 kv = *(const float4*)(Km + gidx);
            const float4 vv = *(const float4*)(Vm + gidx);
            float* kd = Ks + j * 65 + d4 * 4;
            kd[0] = kv.x; kd[1] = kv.y; kd[2] = kv.z; kd[3] = kv.w;
            float* vd = Vs + j * 65 + d4 * 4;
            vd[0] = vv.x; vd[1] = vv.y; vd[2] = vv.z; vd[3] = vv.w;
        }
        __syncthreads();

        float s[4][8];
#pragma unroll
        for (int i = 0; i < 4; i++)
#pragma unroll
            for (int j = 0; j < 8; j++) s[i][j] = 0.f;

#pragma unroll 8
        for (int d = 0; d < 64; d++) {
            float a[4], bb[8];
#pragma unroll
            for (int i = 0; i < 4; i++) a[i] = Qs[(ry * 4 + i) * 65 + d];
#pragma unroll
            for (int j = 0; j < 8; j++) bb[j] = Ks[(cx * 8 + j) * 65 + d];
#pragma unroll
            for (int i = 0; i < 4; i++)
#pragma unroll
                for (int j = 0; j < 8; j++)
                    s[i][j] = fmaf(a[i], bb[j], s[i][j]);
        }

        if (j0 + 64 > qBase) {
#pragma unroll
            for (int i = 0; i < 4; i++) {
                int qg = qBase + ry * 4 + i;
#pragma unroll
                for (int j = 0; j < 8; j++)
                    if (j0 + cx * 8 + j > qg) s[i][j] = -1e30f;
            }
        }

#pragma unroll
        for (int i = 0; i < 4; i++) {
            float rm = s[i][0];
#pragma unroll
            for (int j = 1; j < 8; j++) rm = fmaxf(rm, s[i][j]);
            rm = fmaxf(rm, __shfl_xor_sync(0xffffffffu, rm, 1));
            rm = fmaxf(rm, __shfl_xor_sync(0xffffffffu, rm, 2));
            rm = fmaxf(rm, __shfl_xor_sync(0xffffffffu, rm, 4));
            float mn = fmaxf(m_r[i], rm);
            float scale = __expf(m_r[i] - mn);
            float rs = 0.f;
#pragma unroll
            for (int j = 0; j < 8; j++) {
                float p = __expf(s[i][j] - mn);
                Ps[(ry * 4 + i) * 65 + cx * 8 + j] = p;
                rs += p;
            }
            rs += __shfl_xor_sync(0xffffffffu, rs, 1);
            rs += __shfl_xor_sync(0xffffffffu, rs, 2);
            rs += __shfl_xor_sync(0xffffffffu, rs, 4);
            l_r[i] = l_r[i] * scale + rs;
            m_r[i] = mn;
#pragma unroll
            for (int j = 0; j < 8; j++) oacc[i][j] *= scale;
        }
        __syncwarp();

#pragma unroll 8
        for (int kk = 0; kk < 64; kk++) {
            float a[4], bb[8];
#pragma unroll
            for (int i = 0; i < 4; i++) a[i] = Ps[(ry * 4 + i) * 65 + kk];
#pragma unroll
            for (int j = 0; j < 8; j++) bb[j] = Vs[kk * 65 + cx * 8 + j];
#pragma unroll
            for (int i = 0; i < 4; i++)
#pragma unroll
                for (int j = 0; j < 8; j++)
                    oacc[i][j] = fmaf(a[i], bb[j], oacc[i][j]);
        }
    }

#pragma unroll
    for (int i = 0; i < 4; i++) {
        float inv = 1.f / l_r[i];
        int gi = qBase + ry * 4 + i;
        int tp = segbase + gi * R;
        size_t obase = ((size_t)(b * Tdim + tp) * Cdim) + h * Ddim + cx * 8;
#pragma unroll
        for (int j = 0; j < 8; j++) Obuf[obase + j] = oacc[i][j] * inv;
        if (cx == 0)
            Lbuf[(size_t)(b * Tdim + tp) * Hdim + h] = m_r[i] + __logf(l_r[i]);
    }
}

// ---------------- combine branches -> y (bf16 hi/lo split out) -------------
__global__ __launch_bounds__(256) void combine_kernel(
    const float* __restrict__ O1, const float* __restrict__ O2,
    const float* __restrict__ O3, const float* __restrict__ L1,
    const float* __restrict__ L2, const float* __restrict__ L3,
    __nv_bfloat16* __restrict__ Yh, __nv_bfloat16* __restrict__ Yl)
{
    int idx = blockIdx.x * 256 + threadIdx.x;
    int c = idx & (Cdim - 1);
    int bt = idx >> 10;
    int t = bt & (Tdim - 1);
    int h = c >> 6;
    int li = bt * Hdim + h;

    float l1 = L1[li];
    bool p2 = (((t ^ h) & 1) == 0);
    bool p3 = (((t ^ h) & 3) == 0);
    float l2 = p2 ? L2[li] : -1e30f;
    float l3 = p3 ? L3[li] : -1e30f;
    float m = fmaxf(l1, fmaxf(l2, l3));
    float w1 = __expf(l1 - m);
    float w2 = p2 ? __expf(l2 - m) : 0.f;
    float w3 = p3 ? __expf(l3 - m) : 0.f;
    float num = w1 * O1[idx];
    if (p2) num += w2 * O2[idx];
    if (p3) num += w3 * O3[idx];
    float y = num / (w1 + w2 + w3);
    __nv_bfloat16 hh = __float2bfloat16(y);
    Yh[idx] = hh;
    Yl[idx] = __float2bfloat16(y - __bfloat162float(hh));
}

// ---------------- launcher --------------------------------------------------
extern "C" void kernel_launch(void* const* d_in, const int* in_sizes, int n_in,
                              void* d_out, int out_size)
{
    const float* x        = (const float*)d_in[0];
    const float* c_attn_w = (const float*)d_in[1];
    const float* c_attn_b = (const float*)d_in[2];
    const float* q_w      = (const float*)d_in[3];
    const float* q_b      = (const float*)d_in[4];
    const float* k_w      = (const float*)d_in[5];
    const float* k_b      = (const float*)d_in[6];
    const float* v_w      = (const float*)d_in[7];
    const float* v_b      = (const float*)d_in[8];
    const float* o_w      = (const float*)d_in[9];
    const float* o_b      = (const float*)d_in[10];
    float* out = (float*)d_out;

    __nv_bfloat16 *p_xhi, *p_xlo, *p_cawh, *p_cawl, *p_qwh, *p_qwl, *p_kwh, *p_kwl;
    __nv_bfloat16 *p_vwh, *p_vwl, *p_owh, *p_owl, *p_qkvh, *p_qkvl, *p_yh, *p_yl;
    float *p_q, *p_k, *p_v, *p_o1, *p_o2, *p_o3, *p_l1, *p_l2, *p_l3;
    cudaGetSymbolAddress((void**)&p_xhi, g_xhi);
    cudaGetSymbolAddress((void**)&p_xlo, g_xlo);
    cudaGetSymbolAddress((void**)&p_cawh, g_cawh);
    cudaGetSymbolAddress((void**)&p_cawl, g_cawl);
    cudaGetSymbolAddress((void**)&p_qwh, g_qwh);
    cudaGetSymbolAddress((void**)&p_qwl, g_qwl);
    cudaGetSymbolAddress((void**)&p_kwh, g_kwh);
    cudaGetSymbolAddress((void**)&p_kwl, g_kwl);
    cudaGetSymbolAddress((void**)&p_vwh, g_vwh);
    cudaGetSymbolAddress((void**)&p_vwl, g_vwl);
    cudaGetSymbolAddress((void**)&p_owh, g_owh);
    cudaGetSymbolAddress((void**)&p_owl, g_owl);
    cudaGetSymbolAddress((void**)&p_qkvh, g_qkvh);
    cudaGetSymbolAddress((void**)&p_qkvl, g_qkvl);
    cudaGetSymbolAddress((void**)&p_yh, g_yh);
    cudaGetSymbolAddress((void**)&p_yl, g_yl);
    cudaGetSymbolAddress((void**)&p_q, g_q);
    cudaGetSymbolAddress((void**)&p_k, g_k);
    cudaGetSymbolAddress((void**)&p_v, g_v);
    cudaGetSymbolAddress((void**)&p_o1, g_o1);
    cudaGetSymbolAddress((void**)&p_o2, g_o2);
    cudaGetSymbolAddress((void**)&p_o3, g_o3);
    cudaGetSymbolAddress((void**)&p_l1, g_l1);
    cudaGetSymbolAddress((void**)&p_l2, g_l2);
    cudaGetSymbolAddress((void**)&p_l3, g_l3);

    cudaFuncSetAttribute(attn_branch, cudaFuncAttributeMaxDynamicSharedMemorySize, ATTN_SMEM);
    cudaFuncSetAttribute(hmma_gemm, cudaFuncAttributeMaxDynamicSharedMemorySize, HG_SMEM);

    // conversions
    split_kernel<<<MROWS * Cdim / 1024, 256>>>(x, p_xhi, p_xlo, MROWS * Cdim);
    transpose_split<<<dim3(3 * Cdim / 32, Cdim / 32), dim3(32, 8)>>>(c_attn_w, Cdim, 3 * Cdim, p_cawh, p_cawl);
    transpose_split<<<dim3(Cdim / 32, Cdim / 32), dim3(32, 8)>>>(q_w, Cdim, Cdim, p_qwh, p_qwl);
    transpose_split<<<dim3(Cdim / 32, Cdim / 32), dim3(32, 8)>>>(k_w, Cdim, Cdim, p_kwh, p_kwl);
    transpose_split<<<dim3(Cdim / 32, Cdim / 32), dim3(32, 8)>>>(v_w, Cdim, Cdim, p_vwh, p_vwl);
    transpose_split<<<dim3(Cdim / 32, Cdim / 32), dim3(32, 8)>>>(o_w, Cdim, Cdim, p_owh, p_owl);

    // 1) qkv = x @ c_attn_w + b   -> split bf16 out directly
    hmma_gemm<<<dim3(3 * Cdim / 128, MROWS / 128), 256, HG_SMEM>>>(
        p_xhi, p_xlo, Cdim, p_cawh, p_cawl, Cdim, c_attn_b,
        nullptr, p_qkvh, p_qkvl, 3 * Cdim, Cdim, 1.f, 1);

    // 2) q/k/v projections (q scaled by D^-0.5) -> fp32 out
    hmma_gemm<<<dim3(Cdim / 128, MROWS / 128), 256, HG_SMEM>>>(
        p_qkvh + 0 * Cdim, p_qkvl + 0 * Cdim, 3 * Cdim, p_qwh, p_qwl, Cdim, q_b,
        p_q, nullptr, nullptr, Cdim, Cdim, 0.125f, 0);
    hmma_gemm<<<dim3(Cdim / 128, MROWS / 128), 256, HG_SMEM>>>(
        p_qkvh + 1 * Cdim, p_qkvl + 1 * Cdim, 3 * Cdim, p_kwh, p_kwl, Cdim, k_b,
        p_k, nullptr, nullptr, Cdim, Cdim, 1.f, 0);
    hmma_gemm<<<dim3(Cdim / 128, MROWS / 128), 256, HG_SMEM>>>(
        p_qkvh + 2 * Cdim, p_qkvl + 2 * Cdim, 3 * Cdim, p_vwh, p_vwl, Cdim, v_b,
        p_v, nullptr, nullptr, Cdim, Cdim, 1.f, 0);

    // 3) three dilated-attention branches
    attn_branch<<<dim3(8 * 4, Hdim, Bdim), 256, ATTN_SMEM>>>(
        p_q, p_k, p_v, p_o1, p_l1, 512, 1);
    attn_branch<<<dim3(4 * 4, Hdim, Bdim), 256, ATTN_SMEM>>>(
        p_q, p_k, p_v, p_o2, p_l2, 1024, 2);
    attn_branch<<<dim3(2 * 4, Hdim, Bdim), 256, ATTN_SMEM>>>(
        p_q, p_k, p_v, p_o3, p_l3, 2048, 4);

    // 4) combine -> y (bf16 split)
    combine_kernel<<<(MROWS * Cdim) / 256, 256>>>(
        p_o1, p_o2, p_o3, p_l1, p_l2, p_l3, p_yh, p_yl);

    // 5) out = y @ o_w + o_b (fp32)
    hmma_gemm<<<dim3(Cdim / 128, MROWS / 128), 256, HG_SMEM>>>(
        p_yh, p_yl, Cdim, p_owh, p_owl, Cdim, o_b,
        out, nullptr, nullptr, Cdim, Cdim, 1.f, 0);
}

// round 5
// speedup vs baseline: 3.0393x; 1.5418x over previous
#include <cuda_runtime.h>
#include <cuda_bf16.h>
#include <cstdint>
#include <cstddef>

// Problem constants
#define Bdim 2
#define Tdim 4096
#define Cdim 1024
#define Hdim 16
#define Ddim 64
#define MROWS (Bdim*Tdim)   // 8192

#define LOG2E 1.4426950408889634f
#define LN2F  0.69314718055994531f

// ====================== helpers ============================================
__device__ __forceinline__ uint32_t smem_to_u32(const void* p) {
    uint32_t addr;
    asm("{ .reg .u64 tmp; cvta.to.shared.u64 tmp, %1; cvt.u32.u64 %0, tmp; }"
        : "=r"(addr) : "l"(p));
    return addr;
}
#define SWZ(x) ((x) ^ (((x) >> 3) & 0x70))

__device__ __forceinline__ void cpa16(uint32_t s, const void* g) {
    asm volatile("cp.async.cg.shared.global [%0], [%1], 16;" :: "r"(s), "l"(g));
}
#define CPA_COMMIT() asm volatile("cp.async.commit_group;")
#define CPA_WAIT0()  asm volatile("cp.async.wait_group 0;")

__device__ __forceinline__ void ldm_x4(uint32_t* r, uint32_t addr) {
    asm volatile("ldmatrix.sync.aligned.m8n8.x4.shared.b16 {%0,%1,%2,%3}, [%4];"
        : "=r"(r[0]), "=r"(r[1]), "=r"(r[2]), "=r"(r[3]) : "r"(addr));
}
__device__ __forceinline__ void ldm_x4t(uint32_t* r, uint32_t addr) {
    asm volatile("ldmatrix.sync.aligned.m8n8.x4.trans.shared.b16 {%0,%1,%2,%3}, [%4];"
        : "=r"(r[0]), "=r"(r[1]), "=r"(r[2]), "=r"(r[3]) : "r"(addr));
}
__device__ __forceinline__ void mma16816(float* d, const uint32_t* a, const uint32_t* b) {
    asm volatile(
        "mma.sync.aligned.m16n8k16.row.col.f32.bf16.bf16.f32 "
        "{%0,%1,%2,%3}, {%4,%5,%6,%7}, {%8,%9}, {%0,%1,%2,%3};"
        : "+f"(d[0]), "+f"(d[1]), "+f"(d[2]), "+f"(d[3])
        : "r"(a[0]), "r"(a[1]), "r"(a[2]), "r"(a[3]), "r"(b[0]), "r"(b[1]));
}
__device__ __forceinline__ float ex2f(float x) {
    float y; asm("ex2.approx.ftz.f32 %0, %1;" : "=f"(y) : "f"(x)); return y;
}

// ====================== scratch (static device globals) ====================
__device__ __nv_bfloat16 g_xhi[MROWS * Cdim];
__device__ __nv_bfloat16 g_xlo[MROWS * Cdim];
__device__ __nv_bfloat16 g_cawh[3 * Cdim * Cdim];   // c_attn_w^T
__device__ __nv_bfloat16 g_cawl[3 * Cdim * Cdim];
__device__ __nv_bfloat16 g_qwh[Cdim * Cdim];
__device__ __nv_bfloat16 g_qwl[Cdim * Cdim];
__device__ __nv_bfloat16 g_kwh[Cdim * Cdim];
__device__ __nv_bfloat16 g_kwl[Cdim * Cdim];
__device__ __nv_bfloat16 g_vwh[Cdim * Cdim];
__device__ __nv_bfloat16 g_vwl[Cdim * Cdim];
__device__ __nv_bfloat16 g_owh[Cdim * Cdim];
__device__ __nv_bfloat16 g_owl[Cdim * Cdim];
__device__ __nv_bfloat16 g_qkvh[MROWS * 3 * Cdim];
__device__ __nv_bfloat16 g_qkvl[MROWS * 3 * Cdim];
__device__ __nv_bfloat16 g_qh[MROWS * Cdim];
__device__ __nv_bfloat16 g_ql[MROWS * Cdim];
__device__ __nv_bfloat16 g_kh[MROWS * Cdim];
__device__ __nv_bfloat16 g_kl[MROWS * Cdim];
__device__ __nv_bfloat16 g_vh[MROWS * Cdim];
__device__ __nv_bfloat16 g_vl[MROWS * Cdim];
__device__ __nv_bfloat16 g_yh[MROWS * Cdim];
__device__ __nv_bfloat16 g_yl[MROWS * Cdim];
__device__ float g_o1[MROWS * Cdim];
__device__ float g_o2[MROWS * Cdim];
__device__ float g_o3[MROWS * Cdim];
__device__ float g_l1[MROWS * Hdim];
__device__ float g_l2[MROWS * Hdim];
__device__ float g_l3[MROWS * Hdim];

// ====================== conversion kernels =================================
__global__ __launch_bounds__(256) void split_kernel(
    const float* __restrict__ in, __nv_bfloat16* __restrict__ hi,
    __nv_bfloat16* __restrict__ lo, int n)
{
    int i = (blockIdx.x * 256 + threadIdx.x) * 4;
    if (i >= n) return;
    float4 v = *(const float4*)(in + i);
    float vv[4] = {v.x, v.y, v.z, v.w};
    __nv_bfloat16 h[4], l[4];
#pragma unroll
    for (int k = 0; k < 4; k++) {
        h[k] = __float2bfloat16(vv[k]);
        l[k] = __float2bfloat16(vv[k] - __bfloat162float(h[k]));
    }
    *(uint2*)(hi + i) = *(uint2*)h;
    *(uint2*)(lo + i) = *(uint2*)l;
}

__global__ __launch_bounds__(256) void transpose_split(
    const float* __restrict__ W, int K, int N,
    __nv_bfloat16* __restrict__ Th, __nv_bfloat16* __restrict__ Tl)
{
    __shared__ float tile[32][33];
    int n0 = blockIdx.x * 32, k0 = blockIdx.y * 32;
    int tx = threadIdx.x, ty = threadIdx.y;
#pragma unroll
    for (int r = 0; r < 4; r++)
        tile[ty + r * 8][tx] = W[(size_t)(k0 + ty + r * 8) * N + n0 + tx];
    __syncthreads();
#pragma unroll
    for (int r = 0; r < 4; r++) {
        float v = tile[tx][ty + r * 8];
        __nv_bfloat16 h = __float2bfloat16(v);
        size_t o = (size_t)(n0 + ty + r * 8) * K + k0 + tx;
        Th[o] = h;
        Tl[o] = __float2bfloat16(v - __bfloat162float(h));
    }
}

// ====================== HMMA bf16x3 GEMM ===================================
#define HG_STAGE 65536
#define HG_SMEM  (2 * HG_STAGE)

__device__ __forceinline__ void hg_load_stage(
    uint32_t sbase, int buf,
    const __nv_bfloat16* __restrict__ a_hi, const __nv_bfloat16* __restrict__ a_lo,
    size_t m0, int lda,
    const __nv_bfloat16* __restrict__ b_hi, const __nv_bfloat16* __restrict__ b_lo,
    size_t n0, int ldb, int k0, int tid)
{
    uint32_t sAh = sbase + buf * HG_STAGE;
    uint32_t sAl = sAh + 16384;
    uint32_t sBh = sAh + 32768;
    uint32_t sBl = sAh + 49152;
#pragma unroll
    for (int t = 0; t < 4; t++) {
        int i = tid + t * 256;
        int row = i >> 3, u = i & 7;
        uint32_t soff = SWZ(row * 128 + u * 16);
        size_t ga = (m0 + row) * (size_t)lda + k0 + u * 8;
        size_t gb = (n0 + row) * (size_t)ldb + k0 + u * 8;
        cpa16(sAh + soff, a_hi + ga);
        cpa16(sAl + soff, a_lo + ga);
        cpa16(sBh + soff, b_hi + gb);
        cpa16(sBl + soff, b_lo + gb);
    }
}

__global__ __launch_bounds__(256, 1) void hmma_gemm(
    const __nv_bfloat16* __restrict__ a_hi, const __nv_bfloat16* __restrict__ a_lo, int lda,
    const __nv_bfloat16* __restrict__ b_hi, const __nv_bfloat16* __restrict__ b_lo, int ldb,
    const float* __restrict__ bias,
    float* __restrict__ outf,
    __nv_bfloat16* __restrict__ out_hi, __nv_bfloat16* __restrict__ out_lo,
    int ldc, int K, float alpha, int mode)
{
    extern __shared__ char sm[];
    const uint32_t sbase = smem_to_u32(sm);
    const int tid  = threadIdx.x;
    const int warp = tid >> 5, lane = tid & 31;
    const int wm0 = (warp >> 2) * 64;
    const int wn0 = (warp & 3) * 32;
    const size_t m0 = (size_t)blockIdx.y * 128;
    const size_t n0 = (size_t)blockIdx.x * 128;
    const int NC = K >> 6;

    float acc[4][4][4];
#pragma unroll
    for (int i = 0; i < 4; i++)
#pragma unroll
        for (int j = 0; j < 4; j++)
#pragma unroll
            for (int r = 0; r < 4; r++) acc[i][j][r] = 0.f;

    hg_load_stage(sbase, 0, a_hi, a_lo, m0, lda, b_hi, b_lo, n0, ldb, 0, tid);
    CPA_COMMIT();

    const int g = lane >> 3;
    const int l7 = lane & 7;

    for (int c = 0; c < NC; ++c) {
        CPA_WAIT0();
        __syncthreads();
        if (c + 1 < NC) {
            hg_load_stage(sbase, (c + 1) & 1, a_hi, a_lo, m0, lda,
                          b_hi, b_lo, n0, ldb, (c + 1) * 64, tid);
            CPA_COMMIT();
        }
        uint32_t sAh = sbase + (c & 1) * HG_STAGE;
        uint32_t sAl = sAh + 16384;
        uint32_t sBh = sAh + 32768;
        uint32_t sBl = sAh + 49152;

#pragma unroll
        for (int ks = 0; ks < 4; ks++) {
            uint32_t ah[4][4], al[4][4];
            {
                int arow = wm0 + (g & 1) * 8 + l7;
                int akb  = ks * 32 + ((g >> 1) & 1) * 16;
#pragma unroll
                for (int mt = 0; mt < 4; mt++) {
                    uint32_t off = SWZ((arow + mt * 16) * 128 + akb);
                    ldm_x4(ah[mt], sAh + off);
                    ldm_x4(al[mt], sAl + off);
                }
            }
            uint32_t bh[4][2], bl[4][2];
            {
                int nrow = wn0 + ((g >> 1) & 1) * 8 + l7;
                int bkb  = ks * 32 + (g & 1) * 16;
#pragma unroll
                for (int nt = 0; nt < 2; nt++) {
                    uint32_t off = SWZ((nrow + nt * 16) * 128 + bkb);
                    uint32_t r[4];
                    ldm_x4(r, sBh + off);
                    bh[nt * 2 + 0][0] = r[0]; bh[nt * 2 + 0][1] = r[1];
                    bh[nt * 2 + 1][0] = r[2]; bh[nt * 2 + 1][1] = r[3];
                    ldm_x4(r, sBl + off);
                    bl[nt * 2 + 0][0] = r[0]; bl[nt * 2 + 0][1] = r[1];
                    bl[nt * 2 + 1][0] = r[2]; bl[nt * 2 + 1][1] = r[3];
                }
            }
#pragma unroll
            for (int mt = 0; mt < 4; mt++)
#pragma unroll
                for (int j = 0; j < 4; j++) {
                    mma16816(acc[mt][j], ah[mt], bh[j]);
                    mma16816(acc[mt][j], ah[mt], bl[j]);
                    mma16816(acc[mt][j], al[mt], bh[j]);
                }
        }
        __syncthreads();
    }

    const int qrow = lane >> 2;
    const int qcol = (lane & 3) * 2;
#pragma unroll
    for (int j = 0; j < 4; j++) {
        size_t col = n0 + wn0 + j * 8 + qcol;
        float b0 = bias[col], b1 = bias[col + 1];
#pragma unroll
        for (int mt = 0; mt < 4; mt++) {
            size_t row0 = m0 + wm0 + mt * 16 + qrow;
            size_t row1 = row0 + 8;
            float v00 = alpha * (acc[mt][j][0] + b0);
            float v01 = alpha * (acc[mt][j][1] + b1);
            float v10 = alpha * (acc[mt][j][2] + b0);
            float v11 = alpha * (acc[mt][j][3] + b1);
            if (mode == 0) {
                float2 r0 = {v00, v01}, r1 = {v10, v11};
                *(float2*)(outf + row0 * ldc + col) = r0;
                *(float2*)(outf + row1 * ldc + col) = r1;
            } else {
                __nv_bfloat162 hh0, ll0, hh1, ll1;
                hh0.x = __float2bfloat16(v00); hh0.y = __float2bfloat16(v01);
                ll0.x = __float2bfloat16(v00 - __bfloat162float(hh0.x));
                ll0.y = __float2bfloat16(v01 - __bfloat162float(hh0.y));
                hh1.x = __float2bfloat16(v10); hh1.y = __float2bfloat16(v11);
                ll1.x = __float2bfloat16(v10 - __bfloat162float(hh1.x));
                ll1.y = __float2bfloat16(v11 - __bfloat162float(hh1.y));
                *(uint32_t*)((char*)out_hi + (row0 * ldc + col) * 2) = *(uint32_t*)&hh0;
                *(uint32_t*)((char*)out_lo + (row0 * ldc + col) * 2) = *(uint32_t*)&ll0;
                *(uint32_t*)((char*)out_hi + (row1 * ldc + col) * 2) = *(uint32_t*)&hh1;
                *(uint32_t*)((char*)out_lo + (row1 * ldc + col) * 2) = *(uint32_t*)&ll1;
            }
        }
    }
}

// ================= HMMA dilated attention branch ===========================
// 256 threads, 8 warps x 16 query rows = 128 queries per CTA.
// K-tiles of 64 keys, cp.async double buffer, bf16 hi/lo 3-term MMA.
// Smem: Qh 16K, Ql 16K, then 2 stages x (Kh,Kl,Vh,Vl 8K each) = 96 KB.
#define FA_SMEM 98304

__global__ __launch_bounds__(256) void attn_hmma(
    const __nv_bfloat16* __restrict__ qh_g, const __nv_bfloat16* __restrict__ ql_g,
    const __nv_bfloat16* __restrict__ kh_g, const __nv_bfloat16* __restrict__ kl_g,
    const __nv_bfloat16* __restrict__ vh_g, const __nv_bfloat16* __restrict__ vl_g,
    float* __restrict__ Obuf, float* __restrict__ Lbuf, int W, int R)
{
    extern __shared__ char sm[];
    const uint32_t sbase = smem_to_u32(sm);
    const uint32_t sQh = sbase, sQl = sbase + 16384;

    const int b   = blockIdx.z;
    const int h   = blockIdx.y;
    const int seg = blockIdx.x >> 2;
    const int qt  = blockIdx.x & 3;
    const int tid = threadIdx.x;
    const int warp = tid >> 5, lane = tid & 31;
    const int g = lane >> 3, l7 = lane & 7;
    const int segbase = seg * W + (h & (R - 1));
    const int qBase = qt * 128;
    const size_t hoff = (size_t)h * Ddim;

    // ---- issue Q loads ----
#pragma unroll
    for (int t = 0; t < 4; t++) {
        int i = tid + t * 256;
        int row = i >> 3, u = i & 7;
        int tp = segbase + (qBase + row) * R;
        size_t gidx = (size_t)(b * Tdim + tp) * Cdim + hoff + u * 8;
        uint32_t off = SWZ(row * 128 + u * 16);
        cpa16(sQh + off, qh_g + gidx);
        cpa16(sQl + off, ql_g + gidx);
    }
    // ---- issue K/V tile 0 ----
    {
        uint32_t st = sbase + 32768;
#pragma unroll
        for (int t = 0; t < 2; t++) {
            int i = tid + t * 256;
            int row = i >> 3, u = i & 7;
            int tp = segbase + row * R;
            size_t gidx = (size_t)(b * Tdim + tp) * Cdim + hoff + u * 8;
            uint32_t off = SWZ(row * 128 + u * 16);
            cpa16(st +         off, kh_g + gidx);
            cpa16(st +  8192 + off, kl_g + gidx);
            cpa16(st + 16384 + off, vh_g + gidx);
            cpa16(st + 24576 + off, vl_g + gidx);
        }
    }
    CPA_COMMIT();

    uint32_t qfh[4][4], qfl[4][4];
    float oa[8][4];
#pragma unroll
    for (int nt = 0; nt < 8; nt++)
#pragma unroll
        for (int r = 0; r < 4; r++) oa[nt][r] = 0.f;
    float m0 = -1e30f, m1 = -1e30f, l0 = 0.f, l1 = 0.f;

    const int r0 = lane >> 2;
    const int row0 = qBase + warp * 16 + r0;   // gathered q index
    const int row1 = row0 + 8;
    const int colb = (lane & 3) * 2;

    const int ntiles = qt * 2 + 2;
    for (int jt = 0; jt < ntiles; jt++) {
        const int j0 = jt * 64;
        CPA_WAIT0();
        __syncthreads();
        if (jt == 0) {
            // load Q fragments once
            int arow = warp * 16 + (g & 1) * 8 + l7;
#pragma unroll
            for (int ks = 0; ks < 4; ks++) {
                int akb = ks * 32 + ((g >> 1) & 1) * 16;
                uint32_t off = SWZ(arow * 128 + akb);
                ldm_x4(qfh[ks], sQh + off);
                ldm_x4(qfl[ks], sQl + off);
            }
        }
        if (jt + 1 < ntiles) {
            uint32_t st = sbase + 32768 + ((jt + 1) & 1) * 32768;
            int jn0 = (jt + 1) * 64;
#pragma unroll
            for (int t = 0; t < 2; t++) {
                int i = tid + t * 256;
                int row = i >> 3, u = i & 7;
                int tp = segbase + (jn0 + row) * R;
                size_t gidx = (size_t)(b * Tdim + tp) * Cdim + hoff + u * 8;
                uint32_t off = SWZ(row * 128 + u * 16);
                cpa16(st +         off, kh_g + gidx);
                cpa16(st +  8192 + off, kl_g + gidx);
                cpa16(st + 16384 + off, vh_g + gidx);
                cpa16(st + 24576 + off, vl_g + gidx);
            }
            CPA_COMMIT();
        }

        uint32_t sKh = sbase + 32768 + (jt & 1) * 32768;
        uint32_t sKl = sKh + 8192;
        uint32_t sVh = sKh + 16384;
        uint32_t sVl = sKh + 24576;

        // ---- S = Q K^T ----
        float sa[8][4];
#pragma unroll
        for (int j = 0; j < 8; j++)
#pragma unroll
            for (int r = 0; r < 4; r++) sa[j][r] = 0.f;

#pragma unroll
        for (int ks = 0; ks < 4; ks++) {
            uint32_t kfh[8][2], kfl[8][2];
            int nrow = ((g >> 1) & 1) * 8 + l7;
            int bkb  = ks * 32 + (g & 1) * 16;
#pragma unroll
            for (int nt16 = 0; nt16 < 4; nt16++) {
                uint32_t off = SWZ((nrow + nt16 * 16) * 128 + bkb);
                uint32_t r[4];
                ldm_x4(r, sKh + off);
                kfh[nt16 * 2 + 0][0] = r[0]; kfh[nt16 * 2 + 0][1] = r[1];
                kfh[nt16 * 2 + 1][0] = r[2]; kfh[nt16 * 2 + 1][1] = r[3];
                ldm_x4(r, sKl + off);
                kfl[nt16 * 2 + 0][0] = r[0]; kfl[nt16 * 2 + 0][1] = r[1];
                kfl[nt16 * 2 + 1][0] = r[2]; kfl[nt16 * 2 + 1][1] = r[3];
            }
#pragma unroll
            for (int j = 0; j < 8; j++) {
                mma16816(sa[j], qfh[ks], kfh[j]);
                mma16816(sa[j], qfh[ks], kfl[j]);
                mma16816(sa[j], qfl[ks], kfh[j]);
            }
        }

        // ---- causal mask (last two tiles only) ----
        if (jt >= 2 * qt) {
#pragma unroll
            for (int j = 0; j < 8; j++) {
                int key = j0 + j * 8 + colb;
                if (key     > row0) sa[j][0] = -1e30f;
                if (key + 1 > row0) sa[j][1] = -1e30f;
                if (key     > row1) sa[j][2] = -1e30f;
                if (key + 1 > row1) sa[j][3] = -1e30f;
            }
        }

        // ---- online softmax (log2 domain) ----
        float rm0 = sa[0][0], rm1 = sa[0][2];
#pragma unroll
        for (int j = 0; j < 8; j++) {
            rm0 = fmaxf(rm0, fmaxf(sa[j][0], sa[j][1]));
            rm1 = fmaxf(rm1, fmaxf(sa[j][2], sa[j][3]));
        }
        rm0 = fmaxf(rm0, __shfl_xor_sync(0xffffffffu, rm0, 1));
        rm0 = fmaxf(rm0, __shfl_xor_sync(0xffffffffu, rm0, 2));
        rm1 = fmaxf(rm1, __shfl_xor_sync(0xffffffffu, rm1, 1));
        rm1 = fmaxf(rm1, __shfl_xor_sync(0xffffffffu, rm1, 2));
        float mn0 = fmaxf(m0, rm0), mn1 = fmaxf(m1, rm1);
        float sc0 = ex2f(m0 - mn0), sc1 = ex2f(m1 - mn1);
        float rs0 = 0.f, rs1 = 0.f;
#pragma unroll
        for (int j = 0; j < 8; j++) {
            sa[j][0] = ex2f(sa[j][0] - mn0);
            sa[j][1] = ex2f(sa[j][1] - mn0);
            sa[j][2] = ex2f(sa[j][2] - mn1);
            sa[j][3] = ex2f(sa[j][3] - mn1);
            rs0 += sa[j][0] + sa[j][1];
            rs1 += sa[j][2] + sa[j][3];
        }
        rs0 += __shfl_xor_sync(0xffffffffu, rs0, 1);
        rs0 += __shfl_xor_sync(0xffffffffu, rs0, 2);
        rs1 += __shfl_xor_sync(0xffffffffu, rs1, 1);
        rs1 += __shfl_xor_sync(0xffffffffu, rs1, 2);
        l0 = l0 * sc0 + rs0; l1 = l1 * sc1 + rs1;
        m0 = mn0; m1 = mn1;
#pragma unroll
        for (int nt = 0; nt < 8; nt++) {
            oa[nt][0] *= sc0; oa[nt][1] *= sc0;
            oa[nt][2] *= sc1; oa[nt][3] *= sc1;
        }

        // ---- O += P V ----
#pragma unroll
        for (int kc = 0; kc < 4; kc++) {
            // A-fragments from P (C-layout == A-layout)
            uint32_t ah[4], al[4];
#pragma unroll
            for (int half = 0; half < 2; half++) {
                const float* p0 = sa[kc * 2 + half];
                __nv_bfloat162 h01, h23, lo01, lo23;
                h01.x = __float2bfloat16(p0[0]); h01.y = __float2bfloat16(p0[1]);
                h23.x = __float2bfloat16(p0[2]); h23.y = __float2bfloat16(p0[3]);
                lo01.x = __float2bfloat16(p0[0] - __bfloat162float(h01.x));
                lo01.y = __float2bfloat16(p0[1] - __bfloat162float(h01.y));
                lo23.x = __float2bfloat16(p0[2] - __bfloat162float(h23.x));
                lo23.y = __float2bfloat16(p0[3] - __bfloat162float(h23.y));
                ah[half * 2 + 0] = *(uint32_t*)&h01;
                ah[half * 2 + 1] = *(uint32_t*)&h23;
                al[half * 2 + 0] = *(uint32_t*)&lo01;
                al[half * 2 + 1] = *(uint32_t*)&lo23;
            }
            // swap to A order: a0=(r,k0),a1=(r+8,k0),a2=(r,k8),a3=(r+8,k8)
            // half0 gave (r,k0)(r+8,k0); half1 gave (r,k8)(r+8,k8) -> already correct.

            // V B-fragments via ldmatrix.trans
            uint32_t vfh[8][2], vfl[8][2];
            int vrow = kc * 16 + (g & 1) * 8 + l7;
            int nhalf = (g >> 1) & 1;
#pragma unroll
            for (int nt16 = 0; nt16 < 4; nt16++) {
                uint32_t off = SWZ(vrow * 128 + nt16 * 32 + nhalf * 16);
                uint32_t r[4];
                ldm_x4t(r, sVh + off);
                vfh[nt16 * 2 + 0][0] = r[0]; vfh[nt16 * 2 + 0][1] = r[1];
                vfh[nt16 * 2 + 1][0] = r[2]; vfh[nt16 * 2 + 1][1] = r[3];
                ldm_x4t(r, sVl + off);
                vfl[nt16 * 2 + 0][0] = r[0]; vfl[nt16 * 2 + 0][1] = r[1];
                vfl[nt16 * 2 + 1][0] = r[2]; vfl[nt16 * 2 + 1][1] = r[3];
            }
#pragma unroll
            for (int nt = 0; nt < 8; nt++) {
                mma16816(oa[nt], ah, vfh[nt]);
                mma16816(oa[nt], al, vfh[nt]);
                mma16816(oa[nt], ah, vfl[nt]);
            }
        }
        __syncthreads();
    }

    // ---- epilogue ----
    float inv0 = 1.f / l0, inv1 = 1.f / l1;
    int tp0 = segbase + row0 * R;
    int tp1 = segbase + row1 * R;
    size_t ob0 = (size_t)(b * Tdim + tp0) * Cdim + hoff;
    size_t ob1 = (size_t)(b * Tdim + tp1) * Cdim + hoff;
#pragma unroll
    for (int nt = 0; nt < 8; nt++) {
        int d = nt * 8 + colb;
        float2 w0 = {oa[nt][0] * inv0, oa[nt][1] * inv0};
        float2 w1 = {oa[nt][2] * inv1, oa[nt][3] * inv1};
        *(float2*)(Obuf + ob0 + d) = w0;
        *(float2*)(Obuf + ob1 + d) = w1;
    }
    if ((lane & 3) == 0) {
        Lbuf[(size_t)(b * Tdim + tp0) * Hdim + h] = m0 * LN2F + logf(l0);
        Lbuf[(size_t)(b * Tdim + tp1) * Hdim + h] = m1 * LN2F + logf(l1);
    }
}

// ---------------- combine branches -> y (bf16 hi/lo split out) -------------
__global__ __launch_bounds__(256) void combine_kernel(
    const float* __restrict__ O1, const float* __restrict__ O2,
    const float* __restrict__ O3, const float* __restrict__ L1,
    const float* __restrict__ L2, const float* __restrict__ L3,
    __nv_bfloat16* __restrict__ Yh, __nv_bfloat16* __restrict__ Yl)
{
    int idx = blockIdx.x * 256 + threadIdx.x;
    int c = idx & (Cdim - 1);
    int bt = idx >> 10;
    int t = bt & (Tdim - 1);
    int h = c >> 6;
    int li = bt * Hdim + h;

    float l1 = L1[li];
    bool p2 = (((t ^ h) & 1) == 0);
    bool p3 = (((t ^ h) & 3) == 0);
    float l2 = p2 ? L2[li] : -1e30f;
    float l3 = p3 ? L3[li] : -1e30f;
    float m = fmaxf(l1, fmaxf(l2, l3));
    float w1 = __expf(l1 - m);
    float w2 = p2 ? __expf(l2 - m) : 0.f;
    float w3 = p3 ? __expf(l3 - m) : 0.f;
    float num = w1 * O1[idx];
    if (p2) num += w2 * O2[idx];
    if (p3) num += w3 * O3[idx];
    float y = num / (w1 + w2 + w3);
    __nv_bfloat16 hh = __float2bfloat16(y);
    Yh[idx] = hh;
    Yl[idx] = __float2bfloat16(y - __bfloat162float(hh));
}

// ---------------- launcher --------------------------------------------------
extern "C" void kernel_launch(void* const* d_in, const int* in_sizes, int n_in,
                              void* d_out, int out_size)
{
    const float* x        = (const float*)d_in[0];
    const float* c_attn_w = (const float*)d_in[1];
    const float* c_attn_b = (const float*)d_in[2];
    const float* q_w      = (const float*)d_in[3];
    const float* q_b      = (const float*)d_in[4];
    const float* k_w      = (const float*)d_in[5];
    const float* k_b      = (const float*)d_in[6];
    const float* v_w      = (const float*)d_in[7];
    const float* v_b      = (const float*)d_in[8];
    const float* o_w      = (const float*)d_in[9];
    const float* o_b      = (const float*)d_in[10];
    float* out = (float*)d_out;

    __nv_bfloat16 *p_xhi, *p_xlo, *p_cawh, *p_cawl, *p_qwh, *p_qwl, *p_kwh, *p_kwl;
    __nv_bfloat16 *p_vwh, *p_vwl, *p_owh, *p_owl, *p_qkvh, *p_qkvl, *p_yh, *p_yl;
    __nv_bfloat16 *p_qh, *p_ql, *p_kh, *p_kl, *p_vh, *p_vl;
    float *p_o1, *p_o2, *p_o3, *p_l1, *p_l2, *p_l3;
    cudaGetSymbolAddress((void**)&p_xhi, g_xhi);
    cudaGetSymbolAddress((void**)&p_xlo, g_xlo);
    cudaGetSymbolAddress((void**)&p_cawh, g_cawh);
    cudaGetSymbolAddress((void**)&p_cawl, g_cawl);
    cudaGetSymbolAddress((void**)&p_qwh, g_qwh);
    cudaGetSymbolAddress((void**)&p_qwl, g_qwl);
    cudaGetSymbolAddress((void**)&p_kwh, g_kwh);
    cudaGetSymbolAddress((void**)&p_kwl, g_kwl);
    cudaGetSymbolAddress((void**)&p_vwh, g_vwh);
    cudaGetSymbolAddress((void**)&p_vwl, g_vwl);
    cudaGetSymbolAddress((void**)&p_owh, g_owh);
    cudaGetSymbolAddress((void**)&p_owl, g_owl);
    cudaGetSymbolAddress((void**)&p_qkvh, g_qkvh);
    cudaGetSymbolAddress((void**)&p_qkvl, g_qkvl);
    cudaGetSymbolAddress((void**)&p_yh, g_yh);
    cudaGetSymbolAddress((void**)&p_yl, g_yl);
    cudaGetSymbolAddress((void**)&p_qh, g_qh);
    cudaGetSymbolAddress((void**)&p_ql, g_ql);
    cudaGetSymbolAddress((void**)&p_kh, g_kh);
    cudaGetSymbolAddress((void**)&p_kl, g_kl);
    cudaGetSymbolAddress((void**)&p_vh, g_vh);
    cudaGetSymbolAddress((void**)&p_vl, g_vl);
    cudaGetSymbolAddress((void**)&p_o1, g_o1);
    cudaGetSymbolAddress((void**)&p_o2, g_o2);
    cudaGetSymbolAddress((void**)&p_o3, g_o3);
    cudaGetSymbolAddress((void**)&p_l1, g_l1);
    cudaGetSymbolAddress((void**)&p_l2, g_l2);
    cudaGetSymbolAddress((void**)&p_l3, g_l3);

    cudaFuncSetAttribute(attn_hmma, cudaFuncAttributeMaxDynamicSharedMemorySize, FA_SMEM);
    cudaFuncSetAttribute(hmma_gemm, cudaFuncAttributeMaxDynamicSharedMemorySize, HG_SMEM);

    // conversions
    split_kernel<<<MROWS * Cdim / 1024, 256>>>(x, p_xhi, p_xlo, MROWS * Cdim);
    transpose_split<<<dim3(3 * Cdim / 32, Cdim / 32), dim3(32, 8)>>>(c_attn_w, Cdim, 3 * Cdim, p_cawh, p_cawl);
    transpose_split<<<dim3(Cdim / 32, Cdim / 32), dim3(32, 8)>>>(q_w, Cdim, Cdim, p_qwh, p_qwl);
    transpose_split<<<dim3(Cdim / 32, Cdim / 32), dim3(32, 8)>>>(k_w, Cdim, Cdim, p_kwh, p_kwl);
    transpose_split<<<dim3(Cdim / 32, Cdim / 32), dim3(32, 8)>>>(v_w, Cdim, Cdim, p_vwh, p_vwl);
    transpose_split<<<dim3(Cdim / 32, Cdim / 32), dim3(32, 8)>>>(o_w, Cdim, Cdim, p_owh, p_owl);

    // 1) qkv = x @ c_attn_w + b   -> split bf16
    hmma_gemm<<<dim3(3 * Cdim / 128, MROWS / 128), 256, HG_SMEM>>>(
        p_xhi, p_xlo, Cdim, p_cawh, p_cawl, Cdim, c_attn_b,
        nullptr, p_qkvh, p_qkvl, 3 * Cdim, Cdim, 1.f, 1);

    // 2) q/k/v projections -> split bf16 (q scaled by D^-0.5 * log2e)
    hmma_gemm<<<dim3(Cdim / 128, MROWS / 128), 256, HG_SMEM>>>(
        p_qkvh + 0 * Cdim, p_qkvl + 0 * Cdim, 3 * Cdim, p_qwh, p_qwl, Cdim, q_b,
        nullptr, p_qh, p_ql, Cdim, Cdim, 0.125f * LOG2E, 1);
    hmma_gemm<<<dim3(Cdim / 128, MROWS / 128), 256, HG_SMEM>>>(
        p_qkvh + 1 * Cdim, p_qkvl + 1 * Cdim, 3 * Cdim, p_kwh, p_kwl, Cdim, k_b,
        nullptr, p_kh, p_kl, Cdim, Cdim, 1.f, 1);
    hmma_gemm<<<dim3(Cdim / 128, MROWS / 128), 256, HG_SMEM>>>(
        p_qkvh + 2 * Cdim, p_qkvl + 2 * Cdim, 3 * Cdim, p_vwh, p_vwl, Cdim, v_b,
        nullptr, p_vh, p_vl, Cdim, Cdim, 1.f, 1);

    // 3) three dilated-attention branches (HMMA flash)
    attn_hmma<<<dim3(8 * 4, Hdim, Bdim), 256, FA_SMEM>>>(
        p_qh, p_ql, p_kh, p_kl, p_vh, p_vl, p_o1, p_l1, 512, 1);
    attn_hmma<<<dim3(4 * 4, Hdim, Bdim), 256, FA_SMEM>>>(
        p_qh, p_ql, p_kh, p_kl, p_vh, p_vl, p_o2, p_l2, 1024, 2);
    attn_hmma<<<dim3(2 * 4, Hdim, Bdim), 256, FA_SMEM>>>(
        p_qh, p_ql, p_kh, p_kl, p_vh, p_vl, p_o3, p_l3, 2048, 4);

    // 4) combine -> y (bf16 split)
    combine_kernel<<<(MROWS * Cdim) / 256, 256>>>(
        p_o1, p_o2, p_o3, p_l1, p_l2, p_l3, p_yh, p_yl);

    // 5) out = y @ o_w + o_b (fp32)
    hmma_gemm<<<dim3(Cdim / 128, MROWS / 128), 256, HG_SMEM>>>(
        p_yh, p_yl, Cdim, p_owh, p_owl, Cdim, o_b,
        out, nullptr, nullptr, Cdim, Cdim, 1.f, 0);
}

// round 10
// speedup vs baseline: 4.1195x; 1.3554x over previous
#include <cuda_runtime.h>
#include <cuda_bf16.h>
#include <cstdint>
#include <cstddef>

// Problem constants
#define Bdim 2
#define Tdim 4096
#define Cdim 1024
#define Hdim 16
#define Ddim 64
#define MROWS (Bdim*Tdim)   // 8192
#define PLANE (MROWS*Cdim)
#define WPLANE (Cdim*Cdim)

#define LOG2E 1.4426950408889634f
#define LN2F  0.69314718055994531f

// ====================== helpers ============================================
__device__ __forceinline__ uint32_t smem_to_u32(const void* p) {
    uint32_t addr;
    asm("{ .reg .u64 tmp; cvta.to.shared.u64 tmp, %1; cvt.u32.u64 %0, tmp; }"
        : "=r"(addr) : "l"(p));
    return addr;
}
#define SWZ(x) ((x) ^ (((x) >> 3) & 0x70))

__device__ __forceinline__ void cpa16(uint32_t s, const void* g) {
    asm volatile("cp.async.cg.shared.global [%0], [%1], 16;" :: "r"(s), "l"(g));
}
#define CPA_COMMIT() asm volatile("cp.async.commit_group;")
#define CPA_WAIT0()  asm volatile("cp.async.wait_group 0;")

__device__ __forceinline__ void ldm_x4(uint32_t* r, uint32_t addr) {
    asm volatile("ldmatrix.sync.aligned.m8n8.x4.shared.b16 {%0,%1,%2,%3}, [%4];"
        : "=r"(r[0]), "=r"(r[1]), "=r"(r[2]), "=r"(r[3]) : "r"(addr));
}
__device__ __forceinline__ void ldm_x4t(uint32_t* r, uint32_t addr) {
    asm volatile("ldmatrix.sync.aligned.m8n8.x4.trans.shared.b16 {%0,%1,%2,%3}, [%4];"
        : "=r"(r[0]), "=r"(r[1]), "=r"(r[2]), "=r"(r[3]) : "r"(addr));
}
__device__ __forceinline__ void mma16816(float* d, const uint32_t* a, const uint32_t* b) {
    asm volatile(
        "mma.sync.aligned.m16n8k16.row.col.f32.bf16.bf16.f32 "
        "{%0,%1,%2,%3}, {%4,%5,%6,%7}, {%8,%9}, {%0,%1,%2,%3};"
        : "+f"(d[0]), "+f"(d[1]), "+f"(d[2]), "+f"(d[3])
        : "r"(a[0]), "r"(a[1]), "r"(a[2]), "r"(a[3]), "r"(b[0]), "r"(b[1]));
}
__device__ __forceinline__ float ex2f(float x) {
    float y; asm("ex2.approx.ftz.f32 %0, %1;" : "=f"(y) : "f"(x)); return y;
}

// ====================== scratch (static device globals) ====================
__device__ __nv_bfloat16 g_xhi[PLANE];
__device__ __nv_bfloat16 g_xlo[PLANE];
__device__ __nv_bfloat16 g_cwsh[Cdim * 3 * Cdim];   // c_attn_w split (no transpose)
__device__ __nv_bfloat16 g_cwsl[Cdim * 3 * Cdim];
__device__ __nv_bfloat16 g_wTh[3 * WPLANE];         // q_w^T, k_w^T, v_w^T
__device__ __nv_bfloat16 g_wTl[3 * WPLANE];
__device__ __nv_bfloat16 g_owh[WPLANE];
__device__ __nv_bfloat16 g_owl[WPLANE];
__device__ __nv_bfloat16 g_weffh[3 * WPLANE];       // W_eff^T planes for q,k,v
__device__ __nv_bfloat16 g_weffl[3 * WPLANE];
__device__ float g_beff[3 * Cdim];
__device__ float g_zero[Cdim];                      // zero-initialized
__device__ __nv_bfloat16 g_attnh[3 * PLANE];        // q,k,v hi planes
__device__ __nv_bfloat16 g_attnl[3 * PLANE];
__device__ __nv_bfloat16 g_yh[PLANE];
__device__ __nv_bfloat16 g_yl[PLANE];
__device__ float g_o1[PLANE];
__device__ float g_o2[PLANE];
__device__ float g_o3[PLANE];
__device__ float g_l1[MROWS * Hdim];
__device__ float g_l2[MROWS * Hdim];
__device__ float g_l3[MROWS * Hdim];

// ====================== conversion kernels =================================
__global__ __launch_bounds__(256) void split_kernel(
    const float* __restrict__ in, __nv_bfloat16* __restrict__ hi,
    __nv_bfloat16* __restrict__ lo, int n)
{
    int i = (blockIdx.x * 256 + threadIdx.x) * 4;
    if (i >= n) return;
    float4 v = *(const float4*)(in + i);
    float vv[4] = {v.x, v.y, v.z, v.w};
    __nv_bfloat16 h[4], l[4];
#pragma unroll
    for (int k = 0; k < 4; k++) {
        h[k] = __float2bfloat16(vv[k]);
        l[k] = __float2bfloat16(vv[k] - __bfloat162float(h[k]));
    }
    *(uint2*)(hi + i) = *(uint2*)h;
    *(uint2*)(lo + i) = *(uint2*)l;
}

__global__ __launch_bounds__(256) void transpose_split(
    const float* __restrict__ W, int K, int N,
    __nv_bfloat16* __restrict__ Th, __nv_bfloat16* __restrict__ Tl)
{
    __shared__ float tile[32][33];
    int n0 = blockIdx.x * 32, k0 = blockIdx.y * 32;
    int tx = threadIdx.x, ty = threadIdx.y;
#pragma unroll
    for (int r = 0; r < 4; r++)
        tile[ty + r * 8][tx] = W[(size_t)(k0 + ty + r * 8) * N + n0 + tx];
    __syncthreads();
#pragma unroll
    for (int r = 0; r < 4; r++) {
        float v = tile[tx][ty + r * 8];
        __nv_bfloat16 h = __float2bfloat16(v);
        size_t o = (size_t)(n0 + ty + r * 8) * K + k0 + tx;
        Th[o] = h;
        Tl[o] = __float2bfloat16(v - __bfloat162float(h));
    }
}

// b_eff[z][i] = proj_b[i] + sum_k c_attn_b[z*C+k] * W_z[k][i]
__global__ __launch_bounds__(256) void beff_kernel(
    const float* __restrict__ cab,
    const float* __restrict__ w0, const float* __restrict__ w1, const float* __restrict__ w2,
    const float* __restrict__ b0, const float* __restrict__ b1, const float* __restrict__ b2,
    float* __restrict__ beff)
{
    int i = blockIdx.x * 256 + threadIdx.x;
    int z = blockIdx.y;
    const float* W  = (z == 0) ? w0 : (z == 1) ? w1 : w2;
    const float* bb = (z == 0) ? b0 : (z == 1) ? b1 : b2;
    const float* c = cab + z * Cdim;
    float acc = bb[i];
    for (int k = 0; k < Cdim; k++) acc += c[k] * W[(size_t)k * Cdim + i];
    beff[z * Cdim + i] = acc;
}

// ====================== HMMA bf16x3 GEMM (batched over z) ==================
// C = alpha_z * (A @ B^T + bias); A[M,K] hi/lo, B[N,K] hi/lo; z offsets in elts.
#define HG_STAGE 65536
#define HG_SMEM  (2 * HG_STAGE)

__device__ __forceinline__ void hg_load_stage(
    uint32_t sbase, int buf,
    const __nv_bfloat16* __restrict__ a_hi, const __nv_bfloat16* __restrict__ a_lo,
    size_t m0, int lda,
    const __nv_bfloat16* __restrict__ b_hi, const __nv_bfloat16* __restrict__ b_lo,
    size_t n0, int ldb, int k0, int tid)
{
    uint32_t sAh = sbase + buf * HG_STAGE;
    uint32_t sAl = sAh + 16384;
    uint32_t sBh = sAh + 32768;
    uint32_t sBl = sAh + 49152;
#pragma unroll
    for (int t = 0; t < 4; t++) {
        int i = tid + t * 256;
        int row = i >> 3, u = i & 7;
        uint32_t soff = SWZ(row * 128 + u * 16);
        size_t ga = (m0 + row) * (size_t)lda + k0 + u * 8;
        size_t gb = (n0 + row) * (size_t)ldb + k0 + u * 8;
        cpa16(sAh + soff, a_hi + ga);
        cpa16(sAl + soff, a_lo + ga);
        cpa16(sBh + soff, b_hi + gb);
        cpa16(sBl + soff, b_lo + gb);
    }
}

__global__ __launch_bounds__(256, 1) void hmma_gemm(
    const __nv_bfloat16* __restrict__ a_hi, const __nv_bfloat16* __restrict__ a_lo, int lda,
    const __nv_bfloat16* __restrict__ b_hi, const __nv_bfloat16* __restrict__ b_lo, int ldb,
    const float* __restrict__ bias,
    float* __restrict__ outf,
    __nv_bfloat16* __restrict__ out_hi, __nv_bfloat16* __restrict__ out_lo,
    int ldc, int K, float alpha, float alpha2, int mode,
    int az, int bz, int biasz, int cz)
{
    // batch-z pointer adjustment
    const int z = blockIdx.z;
    a_hi += (size_t)z * az;  a_lo += (size_t)z * az;
    b_hi += (size_t)z * bz;  b_lo += (size_t)z * bz;
    bias += (size_t)z * biasz;
    if (outf)  outf  += (size_t)z * cz;
    if (out_hi) { out_hi += (size_t)z * cz; out_lo += (size_t)z * cz; }
    const float alf = (z == 0) ? alpha : alpha2;

    extern __shared__ char sm[];
    const uint32_t sbase = smem_to_u32(sm);
    const int tid  = threadIdx.x;
    const int warp = tid >> 5, lane = tid & 31;
    const int wm0 = (warp >> 2) * 64;
    const int wn0 = (warp & 3) * 32;
    const size_t m0 = (size_t)blockIdx.y * 128;
    const size_t n0 = (size_t)blockIdx.x * 128;
    const int NC = K >> 6;

    float acc[4][4][4];
#pragma unroll
    for (int i = 0; i < 4; i++)
#pragma unroll
        for (int j = 0; j < 4; j++)
#pragma unroll
            for (int r = 0; r < 4; r++) acc[i][j][r] = 0.f;

    hg_load_stage(sbase, 0, a_hi, a_lo, m0, lda, b_hi, b_lo, n0, ldb, 0, tid);
    CPA_COMMIT();

    const int g = lane >> 3;
    const int l7 = lane & 7;

    for (int c = 0; c < NC; ++c) {
        CPA_WAIT0();
        __syncthreads();
        if (c + 1 < NC) {
            hg_load_stage(sbase, (c + 1) & 1, a_hi, a_lo, m0, lda,
                          b_hi, b_lo, n0, ldb, (c + 1) * 64, tid);
            CPA_COMMIT();
        }
        uint32_t sAh = sbase + (c & 1) * HG_STAGE;
        uint32_t sAl = sAh + 16384;
        uint32_t sBh = sAh + 32768;
        uint32_t sBl = sAh + 49152;

#pragma unroll
        for (int ks = 0; ks < 4; ks++) {
            uint32_t ah[4][4], al[4][4];
            {
                int arow = wm0 + (g & 1) * 8 + l7;
                int akb  = ks * 32 + ((g >> 1) & 1) * 16;
#pragma unroll
                for (int mt = 0; mt < 4; mt++) {
                    uint32_t off = SWZ((arow + mt * 16) * 128 + akb);
                    ldm_x4(ah[mt], sAh + off);
                    ldm_x4(al[mt], sAl + off);
                }
            }
            uint32_t bh[4][2], bl[4][2];
            {
                int nrow = wn0 + ((g >> 1) & 1) * 8 + l7;
                int bkb  = ks * 32 + (g & 1) * 16;
#pragma unroll
                for (int nt = 0; nt < 2; nt++) {
                    uint32_t off = SWZ((nrow + nt * 16) * 128 + bkb);
                    uint32_t r[4];
                    ldm_x4(r, sBh + off);
                    bh[nt * 2 + 0][0] = r[0]; bh[nt * 2 + 0][1] = r[1];
                    bh[nt * 2 + 1][0] = r[2]; bh[nt * 2 + 1][1] = r[3];
                    ldm_x4(r, sBl + off);
                    bl[nt * 2 + 0][0] = r[0]; bl[nt * 2 + 0][1] = r[1];
                    bl[nt * 2 + 1][0] = r[2]; bl[nt * 2 + 1][1] = r[3];
                }
            }
#pragma unroll
            for (int mt = 0; mt < 4; mt++)
#pragma unroll
                for (int j = 0; j < 4; j++) {
                    mma16816(acc[mt][j], ah[mt], bh[j]);
                    mma16816(acc[mt][j], ah[mt], bl[j]);
                    mma16816(acc[mt][j], al[mt], bh[j]);
                }
        }
        __syncthreads();
    }

    const int qrow = lane >> 2;
    const int qcol = (lane & 3) * 2;
#pragma unroll
    for (int j = 0; j < 4; j++) {
        size_t col = n0 + wn0 + j * 8 + qcol;
        float b0 = bias[col], b1 = bias[col + 1];
#pragma unroll
        for (int mt = 0; mt < 4; mt++) {
            size_t row0 = m0 + wm0 + mt * 16 + qrow;
            size_t row1 = row0 + 8;
            float v00 = alf * (acc[mt][j][0] + b0);
            float v01 = alf * (acc[mt][j][1] + b1);
            float v10 = alf * (acc[mt][j][2] + b0);
            float v11 = alf * (acc[mt][j][3] + b1);
            if (mode == 0) {
                float2 r0 = {v00, v01}, r1 = {v10, v11};
                *(float2*)(outf + row0 * ldc + col) = r0;
                *(float2*)(outf + row1 * ldc + col) = r1;
            } else {
                __nv_bfloat162 hh0, ll0, hh1, ll1;
                hh0.x = __float2bfloat16(v00); hh0.y = __float2bfloat16(v01);
                ll0.x = __float2bfloat16(v00 - __bfloat162float(hh0.x));
                ll0.y = __float2bfloat16(v01 - __bfloat162float(hh0.y));
                hh1.x = __float2bfloat16(v10); hh1.y = __float2bfloat16(v11);
                ll1.x = __float2bfloat16(v10 - __bfloat162float(hh1.x));
                ll1.y = __float2bfloat16(v11 - __bfloat162float(hh1.y));
                *(uint32_t*)((char*)out_hi + (row0 * ldc + col) * 2) = *(uint32_t*)&hh0;
                *(uint32_t*)((char*)out_lo + (row0 * ldc + col) * 2) = *(uint32_t*)&ll0;
                *(uint32_t*)((char*)out_hi + (row1 * ldc + col) * 2) = *(uint32_t*)&hh1;
                *(uint32_t*)((char*)out_lo + (row1 * ldc + col) * 2) = *(uint32_t*)&ll1;
            }
        }
    }
}

// ================= HMMA dilated attention branch ===========================
#define FA_SMEM 98304

__global__ __launch_bounds__(256) void attn_hmma(
    const __nv_bfloat16* __restrict__ qh_g, const __nv_bfloat16* __restrict__ ql_g,
    const __nv_bfloat16* __restrict__ kh_g, const __nv_bfloat16* __restrict__ kl_g,
    const __nv_bfloat16* __restrict__ vh_g, const __nv_bfloat16* __restrict__ vl_g,
    float* __restrict__ Obuf, float* __restrict__ Lbuf, int W, int R)
{
    extern __shared__ char sm[];
    const uint32_t sbase = smem_to_u32(sm);
    const uint32_t sQh = sbase, sQl = sbase + 16384;

    const int b   = blockIdx.z;
    const int h   = blockIdx.y;
    const int seg = blockIdx.x >> 2;
    const int qt  = blockIdx.x & 3;
    const int tid = threadIdx.x;
    const int warp = tid >> 5, lane = tid & 31;
    const int g = lane >> 3, l7 = lane & 7;
    const int segbase = seg * W + (h & (R - 1));
    const int qBase = qt * 128;
    const size_t hoff = (size_t)h * Ddim;

#pragma unroll
    for (int t = 0; t < 4; t++) {
        int i = tid + t * 256;
        int row = i >> 3, u = i & 7;
        int tp = segbase + (qBase + row) * R;
        size_t gidx = (size_t)(b * Tdim + tp) * Cdim + hoff + u * 8;
        uint32_t off = SWZ(row * 128 + u * 16);
        cpa16(sQh + off, qh_g + gidx);
        cpa16(sQl + off, ql_g + gidx);
    }
    {
        uint32_t st = sbase + 32768;
#pragma unroll
        for (int t = 0; t < 2; t++) {
            int i = tid + t * 256;
            int row = i >> 3, u = i & 7;
            int tp = segbase + row * R;
            size_t gidx = (size_t)(b * Tdim + tp) * Cdim + hoff + u * 8;
            uint32_t off = SWZ(row * 128 + u * 16);
            cpa16(st +         off, kh_g + gidx);
            cpa16(st +  8192 + off, kl_g + gidx);
            cpa16(st + 16384 + off, vh_g + gidx);
            cpa16(st + 24576 + off, vl_g + gidx);
        }
    }
    CPA_COMMIT();

    uint32_t qfh[4][4], qfl[4][4];
    float oa[8][4];
#pragma unroll
    for (int nt = 0; nt < 8; nt++)
#pragma unroll
        for (int r = 0; r < 4; r++) oa[nt][r] = 0.f;
    float m0 = -1e30f, m1 = -1e30f, l0 = 0.f, l1 = 0.f;

    const int r0 = lane >> 2;
    const int row0 = qBase + warp * 16 + r0;
    const int row1 = row0 + 8;
    const int colb = (lane & 3) * 2;

    const int ntiles = qt * 2 + 2;
    for (int jt = 0; jt < ntiles; jt++) {
        const int j0 = jt * 64;
        CPA_WAIT0();
        __syncthreads();
        if (jt == 0) {
            int arow = warp * 16 + (g & 1) * 8 + l7;
#pragma unroll
            for (int ks = 0; ks < 4; ks++) {
                int akb = ks * 32 + ((g >> 1) & 1) * 16;
                uint32_t off = SWZ(arow * 128 + akb);
                ldm_x4(qfh[ks], sQh + off);
                ldm_x4(qfl[ks], sQl + off);
            }
        }
        if (jt + 1 < ntiles) {
            uint32_t st = sbase + 32768 + ((jt + 1) & 1) * 32768;
            int jn0 = (jt + 1) * 64;
#pragma unroll
            for (int t = 0; t < 2; t++) {
                int i = tid + t * 256;
                int row = i >> 3, u = i & 7;
                int tp = segbase + (jn0 + row) * R;
                size_t gidx = (size_t)(b * Tdim + tp) * Cdim + hoff + u * 8;
                uint32_t off = SWZ(row * 128 + u * 16);
                cpa16(st +         off, kh_g + gidx);
                cpa16(st +  8192 + off, kl_g + gidx);
                cpa16(st + 16384 + off, vh_g + gidx);
                cpa16(st + 24576 + off, vl_g + gidx);
            }
            CPA_COMMIT();
        }

        uint32_t sKh = sbase + 32768 + (jt & 1) * 32768;
        uint32_t sKl = sKh + 8192;
        uint32_t sVh = sKh + 16384;
        uint32_t sVl = sKh + 24576;

        float sa[8][4];
#pragma unroll
        for (int j = 0; j < 8; j++)
#pragma unroll
            for (int r = 0; r < 4; r++) sa[j][r] = 0.f;

#pragma unroll
        for (int ks = 0; ks < 4; ks++) {
            uint32_t kfh[8][2], kfl[8][2];
            int nrow = ((g >> 1) & 1) * 8 + l7;
            int bkb  = ks * 32 + (g & 1) * 16;
#pragma unroll
            for (int nt16 = 0; nt16 < 4; nt16++) {
                uint32_t off = SWZ((nrow + nt16 * 16) * 128 + bkb);
                uint32_t r[4];
                ldm_x4(r, sKh + off);
                kfh[nt16 * 2 + 0][0] = r[0]; kfh[nt16 * 2 + 0][1] = r[1];
                kfh[nt16 * 2 + 1][0] = r[2]; kfh[nt16 * 2 + 1][1] = r[3];
                ldm_x4(r, sKl + off);
                kfl[nt16 * 2 + 0][0] = r[0]; kfl[nt16 * 2 + 0][1] = r[1];
                kfl[nt16 * 2 + 1][0] = r[2]; kfl[nt16 * 2 + 1][1] = r[3];
            }
#pragma unroll
            for (int j = 0; j < 8; j++) {
                mma16816(sa[j], qfh[ks], kfh[j]);
                mma16816(sa[j], qfh[ks], kfl[j]);
                mma16816(sa[j], qfl[ks], kfh[j]);
            }
        }

        if (jt >= 2 * qt) {
#pragma unroll
            for (int j = 0; j < 8; j++) {
                int key = j0 + j * 8 + colb;
                if (key     > row0) sa[j][0] = -1e30f;
                if (key + 1 > row0) sa[j][1] = -1e30f;
                if (key     > row1) sa[j][2] = -1e30f;
                if (key + 1 > row1) sa[j][3] = -1e30f;
            }
        }

        float rm0 = sa[0][0], rm1 = sa[0][2];
#pragma unroll
        for (int j = 0; j < 8; j++) {
            rm0 = fmaxf(rm0, fmaxf(sa[j][0], sa[j][1]));
            rm1 = fmaxf(rm1, fmaxf(sa[j][2], sa[j][3]));
        }
        rm0 = fmaxf(rm0, __shfl_xor_sync(0xffffffffu, rm0, 1));
        rm0 = fmaxf(rm0, __shfl_xor_sync(0xffffffffu, rm0, 2));
        rm1 = fmaxf(rm1, __shfl_xor_sync(0xffffffffu, rm1, 1));
        rm1 = fmaxf(rm1, __shfl_xor_sync(0xffffffffu, rm1, 2));
        float mn0 = fmaxf(m0, rm0), mn1 = fmaxf(m1, rm1);
        float sc0 = ex2f(m0 - mn0), sc1 = ex2f(m1 - mn1);
        float rs0 = 0.f, rs1 = 0.f;
#pragma unroll
        for (int j = 0; j < 8; j++) {
            sa[j][0] = ex2f(sa[j][0] - mn0);
            sa[j][1] = ex2f(sa[j][1] - mn0);
            sa[j][2] = ex2f(sa[j][2] - mn1);
            sa[j][3] = ex2f(sa[j][3] - mn1);
            rs0 += sa[j][0] + sa[j][1];
            rs1 += sa[j][2] + sa[j][3];
        }
        rs0 += __shfl_xor_sync(0xffffffffu, rs0, 1);
        rs0 += __shfl_xor_sync(0xffffffffu, rs0, 2);
        rs1 += __shfl_xor_sync(0xffffffffu, rs1, 1);
        rs1 += __shfl_xor_sync(0xffffffffu, rs1, 2);
        l0 = l0 * sc0 + rs0; l1 = l1 * sc1 + rs1;
        m0 = mn0; m1 = mn1;
#pragma unroll
        for (int nt = 0; nt < 8; nt++) {
            oa[nt][0] *= sc0; oa[nt][1] *= sc0;
            oa[nt][2] *= sc1; oa[nt][3] *= sc1;
        }

#pragma unroll
        for (int kc = 0; kc < 4; kc++) {
            uint32_t ah[4], al[4];
#pragma unroll
            for (int half = 0; half < 2; half++) {
                const float* p0 = sa[kc * 2 + half];
                __nv_bfloat162 h01, h23, lo01, lo23;
                h01.x = __float2bfloat16(p0[0]); h01.y = __float2bfloat16(p0[1]);
                h23.x = __float2bfloat16(p0[2]); h23.y = __float2bfloat16(p0[3]);
                lo01.x = __float2bfloat16(p0[0] - __bfloat162float(h01.x));
                lo01.y = __float2bfloat16(p0[1] - __bfloat162float(h01.y));
                lo23.x = __float2bfloat16(p0[2] - __bfloat162float(h23.x));
                lo23.y = __float2bfloat16(p0[3] - __bfloat162float(h23.y));
                ah[half * 2 + 0] = *(uint32_t*)&h01;
                ah[half * 2 + 1] = *(uint32_t*)&h23;
                al[half * 2 + 0] = *(uint32_t*)&lo01;
                al[half * 2 + 1] = *(uint32_t*)&lo23;
            }

            uint32_t vfh[8][2], vfl[8][2];
            int vrow = kc * 16 + (g & 1) * 8 + l7;
            int nhalf = (g >> 1) & 1;
#pragma unroll
            for (int nt16 = 0; nt16 < 4; nt16++) {
                uint32_t off = SWZ(vrow * 128 + nt16 * 32 + nhalf * 16);
                uint32_t r[4];
                ldm_x4t(r, sVh + off);
                vfh[nt16 * 2 + 0][0] = r[0]; vfh[nt16 * 2 + 0][1] = r[1];
                vfh[nt16 * 2 + 1][0] = r[2]; vfh[nt16 * 2 + 1][1] = r[3];
                ldm_x4t(r, sVl + off);
                vfl[nt16 * 2 + 0][0] = r[0]; vfl[nt16 * 2 + 0][1] = r[1];
                vfl[nt16 * 2 + 1][0] = r[2]; vfl[nt16 * 2 + 1][1] = r[3];
            }
#pragma unroll
            for (int nt = 0; nt < 8; nt++) {
                mma16816(oa[nt], ah, vfh[nt]);
                mma16816(oa[nt], al, vfh[nt]);
                mma16816(oa[nt], ah, vfl[nt]);
            }
        }
        __syncthreads();
    }

    float inv0 = 1.f / l0, inv1 = 1.f / l1;
    int tp0 = segbase + row0 * R;
    int tp1 = segbase + row1 * R;
    size_t ob0 = (size_t)(b * Tdim + tp0) * Cdim + hoff;
    size_t ob1 = (size_t)(b * Tdim + tp1) * Cdim + hoff;
#pragma unroll
    for (int nt = 0; nt < 8; nt++) {
        int d = nt * 8 + colb;
        float2 w0 = {oa[nt][0] * inv0, oa[nt][1] * inv0};
        float2 w1 = {oa[nt][2] * inv1, oa[nt][3] * inv1};
        *(float2*)(Obuf + ob0 + d) = w0;
        *(float2*)(Obuf + ob1 + d) = w1;
    }
    if ((lane & 3) == 0) {
        Lbuf[(size_t)(b * Tdim + tp0) * Hdim + h] = m0 * LN2F + logf(l0);
        Lbuf[(size_t)(b * Tdim + tp1) * Hdim + h] = m1 * LN2F + logf(l1);
    }
}

// ---------------- combine branches -> y (bf16 hi/lo split out) -------------
__global__ __launch_bounds__(256) void combine_kernel(
    const float* __restrict__ O1, const float* __restrict__ O2,
    const float* __restrict__ O3, const float* __restrict__ L1,
    const float* __restrict__ L2, const float* __restrict__ L3,
    __nv_bfloat16* __restrict__ Yh, __nv_bfloat16* __restrict__ Yl)
{
    int idx = blockIdx.x * 256 + threadIdx.x;
    int c = idx & (Cdim - 1);
    int bt = idx >> 10;
    int t = bt & (Tdim - 1);
    int h = c >> 6;
    int li = bt * Hdim + h;

    float l1 = L1[li];
    bool p2 = (((t ^ h) & 1) == 0);
    bool p3 = (((t ^ h) & 3) == 0);
    float l2 = p2 ? L2[li] : -1e30f;
    float l3 = p3 ? L3[li] : -1e30f;
    float m = fmaxf(l1, fmaxf(l2, l3));
    float w1 = __expf(l1 - m);
    float w2 = p2 ? __expf(l2 - m) : 0.f;
    float w3 = p3 ? __expf(l3 - m) : 0.f;
    float num = w1 * O1[idx];
    if (p2) num += w2 * O2[idx];
    if (p3) num += w3 * O3[idx];
    float y = num / (w1 + w2 + w3);
    __nv_bfloat16 hh = __float2bfloat16(y);
    Yh[idx] = hh;
    Yl[idx] = __float2bfloat16(y - __bfloat162float(hh));
}

// ---------------- launcher --------------------------------------------------
extern "C" void kernel_launch(void* const* d_in, const int* in_sizes, int n_in,
                              void* d_out, int out_size)
{
    const float* x        = (const float*)d_in[0];
    const float* c_attn_w = (const float*)d_in[1];
    const float* c_attn_b = (const float*)d_in[2];
    const float* q_w      = (const float*)d_in[3];
    const float* q_b      = (const float*)d_in[4];
    const float* k_w      = (const float*)d_in[5];
    const float* k_b      = (const float*)d_in[6];
    const float* v_w      = (const float*)d_in[7];
    const float* v_b      = (const float*)d_in[8];
    const float* o_w      = (const float*)d_in[9];
    const float* o_b      = (const float*)d_in[10];
    float* out = (float*)d_out;

    __nv_bfloat16 *p_xhi, *p_xlo, *p_cwsh, *p_cwsl, *p_wTh, *p_wTl, *p_owh, *p_owl;
    __nv_bfloat16 *p_weffh, *p_weffl, *p_attnh, *p_attnl, *p_yh, *p_yl;
    float *p_beff, *p_zero, *p_o1, *p_o2, *p_o3, *p_l1, *p_l2, *p_l3;
    cudaGetSymbolAddress((void**)&p_xhi, g_xhi);
    cudaGetSymbolAddress((void**)&p_xlo, g_xlo);
    cudaGetSymbolAddress((void**)&p_cwsh, g_cwsh);
    cudaGetSymbolAddress((void**)&p_cwsl, g_cwsl);
    cudaGetSymbolAddress((void**)&p_wTh, g_wTh);
    cudaGetSymbolAddress((void**)&p_wTl, g_wTl);
    cudaGetSymbolAddress((void**)&p_owh, g_owh);
    cudaGetSymbolAddress((void**)&p_owl, g_owl);
    cudaGetSymbolAddress((void**)&p_weffh, g_weffh);
    cudaGetSymbolAddress((void**)&p_weffl, g_weffl);
    cudaGetSymbolAddress((void**)&p_beff, g_beff);
    cudaGetSymbolAddress((void**)&p_zero, g_zero);
    cudaGetSymbolAddress((void**)&p_attnh, g_attnh);
    cudaGetSymbolAddress((void**)&p_attnl, g_attnl);
    cudaGetSymbolAddress((void**)&p_yh, g_yh);
    cudaGetSymbolAddress((void**)&p_yl, g_yl);
    cudaGetSymbolAddress((void**)&p_o1, g_o1);
    cudaGetSymbolAddress((void**)&p_o2, g_o2);
    cudaGetSymbolAddress((void**)&p_o3, g_o3);
    cudaGetSymbolAddress((void**)&p_l1, g_l1);
    cudaGetSymbolAddress((void**)&p_l2, g_l2);
    cudaGetSymbolAddress((void**)&p_l3, g_l3);

    cudaFuncSetAttribute(attn_hmma, cudaFuncAttributeMaxDynamicSharedMemorySize, FA_SMEM);
    cudaFuncSetAttribute(hmma_gemm, cudaFuncAttributeMaxDynamicSharedMemorySize, HG_SMEM);

    // ---- conversions ----
    split_kernel<<<PLANE / 1024, 256>>>(x, p_xhi, p_xlo, PLANE);
    split_kernel<<<(Cdim * 3 * Cdim) / 1024, 256>>>(c_attn_w, p_cwsh, p_cwsl, Cdim * 3 * Cdim);
    transpose_split<<<dim3(Cdim / 32, Cdim / 32), dim3(32, 8)>>>(q_w, Cdim, Cdim, p_wTh + 0 * WPLANE, p_wTl + 0 * WPLANE);
    transpose_split<<<dim3(Cdim / 32, Cdim / 32), dim3(32, 8)>>>(k_w, Cdim, Cdim, p_wTh + 1 * WPLANE, p_wTl + 1 * WPLANE);
    transpose_split<<<dim3(Cdim / 32, Cdim / 32), dim3(32, 8)>>>(v_w, Cdim, Cdim, p_wTh + 2 * WPLANE, p_wTl + 2 * WPLANE);
    transpose_split<<<dim3(Cdim / 32, Cdim / 32), dim3(32, 8)>>>(o_w, Cdim, Cdim, p_owh, p_owl);
    beff_kernel<<<dim3(Cdim / 256, 3), 256>>>(c_attn_b, q_w, k_w, v_w, q_b, k_b, v_b, p_beff);

    // ---- weight combine: W_eff^T[z] = wT[z] @ cw_slice[z]^T  (batched z=3) --
    // A = wT planes [1024,1024]; B = c_attn_w rows with col-offset z*1024, ldb=3072.
    hmma_gemm<<<dim3(Cdim / 128, Cdim / 128, 3), 256, HG_SMEM>>>(
        p_wTh, p_wTl, Cdim, p_cwsh, p_cwsl, 3 * Cdim, p_zero,
        nullptr, p_weffh, p_weffl, Cdim, Cdim, 1.f, 1.f, 1,
        WPLANE, Cdim, 0, WPLANE);

    // ---- fused q/k/v projections: attn[z] = x @ W_eff[z]^T + b_eff[z] ------
    // z=0 (q) scaled by D^-0.5 * log2e; z=1,2 alpha=1.
    hmma_gemm<<<dim3(Cdim / 128, MROWS / 128, 3), 256, HG_SMEM>>>(
        p_xhi, p_xlo, Cdim, p_weffh, p_weffl, Cdim, p_beff,
        nullptr, p_attnh, p_attnl, Cdim, Cdim, 0.125f * LOG2E, 1.f, 1,
        0, WPLANE, Cdim, PLANE);

    __nv_bfloat16* p_qh = p_attnh + 0 * PLANE; __nv_bfloat16* p_ql = p_attnl + 0 * PLANE;
    __nv_bfloat16* p_kh = p_attnh + 1 * PLANE; __nv_bfloat16* p_kl = p_attnl + 1 * PLANE;
    __nv_bfloat16* p_vh = p_attnh + 2 * PLANE; __nv_bfloat16* p_vl = p_attnl + 2 * PLANE;

    // ---- three dilated-attention branches (HMMA flash) ----
    attn_hmma<<<dim3(8 * 4, Hdim, Bdim), 256, FA_SMEM>>>(
        p_qh, p_ql, p_kh, p_kl, p_vh, p_vl, p_o1, p_l1, 512, 1);
    attn_hmma<<<dim3(4 * 4, Hdim, Bdim), 256, FA_SMEM>>>(
        p_qh, p_ql, p_kh, p_kl, p_vh, p_vl, p_o2, p_l2, 1024, 2);
    attn_hmma<<<dim3(2 * 4, Hdim, Bdim), 256, FA_SMEM>>>(
        p_qh, p_ql, p_kh, p_kl, p_vh, p_vl, p_o3, p_l3, 2048, 4);

    // ---- combine -> y (bf16 split) ----
    combine_kernel<<<PLANE / 256, 256>>>(
        p_o1, p_o2, p_o3, p_l1, p_l2, p_l3, p_yh, p_yl);

    // ---- out = y @ o_w + o_b (fp32) ----
    hmma_gemm<<<dim3(Cdim / 128, MROWS / 128, 1), 256, HG_SMEM>>>(
        p_yh, p_yl, Cdim, p_owh, p_owl, Cdim, o_b,
        out, nullptr, nullptr, Cdim, Cdim, 1.f, 1.f, 0,
        0, 0, 0, 0);
}

// round 11
// speedup vs baseline: 4.3583x; 1.0580x over previous
#include <cuda_runtime.h>
#include <cuda_bf16.h>
#include <cstdint>
#include <cstddef>

// Problem constants
#define Bdim 2
#define Tdim 4096
#define Cdim 1024
#define Hdim 16
#define Ddim 64
#define MROWS (Bdim*Tdim)   // 8192
#define PLANE (MROWS*Cdim)
#define WPLANE (Cdim*Cdim)

#define LOG2E 1.4426950408889634f
#define LN2F  0.69314718055994531f

// ====================== helpers ============================================
__device__ __forceinline__ uint32_t smem_to_u32(const void* p) {
    uint32_t addr;
    asm("{ .reg .u64 tmp; cvta.to.shared.u64 tmp, %1; cvt.u32.u64 %0, tmp; }"
        : "=r"(addr) : "l"(p));
    return addr;
}
#define SWZ(x) ((x) ^ (((x) >> 3) & 0x70))

__device__ __forceinline__ void cpa16(uint32_t s, const void* g) {
    asm volatile("cp.async.cg.shared.global [%0], [%1], 16;" :: "r"(s), "l"(g));
}
#define CPA_COMMIT() asm volatile("cp.async.commit_group;")
#define CPA_WAIT0()  asm volatile("cp.async.wait_group 0;")
#define CPA_WAIT1()  asm volatile("cp.async.wait_group 1;")

__device__ __forceinline__ void ldm_x4(uint32_t* r, uint32_t addr) {
    asm volatile("ldmatrix.sync.aligned.m8n8.x4.shared.b16 {%0,%1,%2,%3}, [%4];"
        : "=r"(r[0]), "=r"(r[1]), "=r"(r[2]), "=r"(r[3]) : "r"(addr));
}
__device__ __forceinline__ void ldm_x4t(uint32_t* r, uint32_t addr) {
    asm volatile("ldmatrix.sync.aligned.m8n8.x4.trans.shared.b16 {%0,%1,%2,%3}, [%4];"
        : "=r"(r[0]), "=r"(r[1]), "=r"(r[2]), "=r"(r[3]) : "r"(addr));
}
__device__ __forceinline__ void mma16816(float* d, const uint32_t* a, const uint32_t* b) {
    asm volatile(
        "mma.sync.aligned.m16n8k16.row.col.f32.bf16.bf16.f32 "
        "{%0,%1,%2,%3}, {%4,%5,%6,%7}, {%8,%9}, {%0,%1,%2,%3};"
        : "+f"(d[0]), "+f"(d[1]), "+f"(d[2]), "+f"(d[3])
        : "r"(a[0]), "r"(a[1]), "r"(a[2]), "r"(a[3]), "r"(b[0]), "r"(b[1]));
}
__device__ __forceinline__ float ex2f(float x) {
    float y; asm("ex2.approx.ftz.f32 %0, %1;" : "=f"(y) : "f"(x)); return y;
}

// ====================== scratch (static device globals) ====================
__device__ __nv_bfloat16 g_xhi[PLANE];
__device__ __nv_bfloat16 g_xlo[PLANE];
__device__ __nv_bfloat16 g_cwsh[Cdim * 3 * Cdim];   // c_attn_w split (no transpose)
__device__ __nv_bfloat16 g_cwsl[Cdim * 3 * Cdim];
__device__ __nv_bfloat16 g_wTh[4 * WPLANE];         // q_w^T, k_w^T, v_w^T, o_w^T
__device__ __nv_bfloat16 g_wTl[4 * WPLANE];
__device__ __nv_bfloat16 g_weffh[3 * WPLANE];       // W_eff^T planes for q,k,v
__device__ __nv_bfloat16 g_weffl[3 * WPLANE];
__device__ float g_beff[3 * Cdim];
__device__ float g_zero[Cdim];                      // zero-initialized
__device__ __nv_bfloat16 g_attnh[3 * PLANE];        // q,k,v hi planes
__device__ __nv_bfloat16 g_attnl[3 * PLANE];
__device__ __nv_bfloat16 g_yh[PLANE];
__device__ __nv_bfloat16 g_yl[PLANE];
__device__ float g_o1[PLANE];
__device__ float g_o2[PLANE];
__device__ float g_o3[PLANE];
__device__ float g_l1[MROWS * Hdim];
__device__ float g_l2[MROWS * Hdim];
__device__ float g_l3[MROWS * Hdim];

// ====================== conversion kernels =================================
// One launch: blocks [0, PLANE/1024) split x; remaining split c_attn_w.
__global__ __launch_bounds__(256) void split2_kernel(
    const float* __restrict__ x, __nv_bfloat16* __restrict__ xh, __nv_bfloat16* __restrict__ xl,
    const float* __restrict__ w, __nv_bfloat16* __restrict__ wh, __nv_bfloat16* __restrict__ wl)
{
    const int XB = PLANE / 1024;
    int bid = blockIdx.x;
    const float* in; __nv_bfloat16 *hi, *lo;
    if (bid < XB) { in = x; hi = xh; lo = xl; }
    else { bid -= XB; in = w; hi = wh; lo = wl; }
    int i = (bid * 256 + threadIdx.x) * 4;
    float4 v = *(const float4*)(in + i);
    float vv[4] = {v.x, v.y, v.z, v.w};
    __nv_bfloat16 h[4], l[4];
#pragma unroll
    for (int k = 0; k < 4; k++) {
        h[k] = __float2bfloat16(vv[k]);
        l[k] = __float2bfloat16(vv[k] - __bfloat162float(h[k]));
    }
    *(uint2*)(hi + i) = *(uint2*)h;
    *(uint2*)(lo + i) = *(uint2*)l;
}

// Batched: z in {0..3} selects q_w,k_w,v_w,o_w -> plane z of Th/Tl (all 1024x1024)
__global__ __launch_bounds__(256) void transpose_split4(
    const float* __restrict__ w0, const float* __restrict__ w1,
    const float* __restrict__ w2, const float* __restrict__ w3,
    __nv_bfloat16* __restrict__ Th, __nv_bfloat16* __restrict__ Tl)
{
    __shared__ float tile[32][33];
    const int z = blockIdx.z;
    const float* W = (z == 0) ? w0 : (z == 1) ? w1 : (z == 2) ? w2 : w3;
    __nv_bfloat16* th = Th + (size_t)z * WPLANE;
    __nv_bfloat16* tl = Tl + (size_t)z * WPLANE;
    int n0 = blockIdx.x * 32, k0 = blockIdx.y * 32;
    int tx = threadIdx.x & 31, ty = threadIdx.x >> 5;
#pragma unroll
    for (int r = 0; r < 4; r++)
        tile[ty + r * 8][tx] = W[(size_t)(k0 + ty + r * 8) * Cdim + n0 + tx];
    __syncthreads();
#pragma unroll
    for (int r = 0; r < 4; r++) {
        float v = tile[tx][ty + r * 8];
        __nv_bfloat16 h = __float2bfloat16(v);
        size_t o = (size_t)(n0 + ty + r * 8) * Cdim + k0 + tx;
        th[o] = h;
        tl[o] = __float2bfloat16(v - __bfloat162float(h));
    }
}

// b_eff[z][i] = proj_b[i] + sum_k c_attn_b[z*C+k] * W_z[k][i]
__global__ __launch_bounds__(256) void beff_kernel(
    const float* __restrict__ cab,
    const float* __restrict__ w0, const float* __restrict__ w1, const float* __restrict__ w2,
    const float* __restrict__ b0, const float* __restrict__ b1, const float* __restrict__ b2,
    float* __restrict__ beff)
{
    int i = blockIdx.x * 256 + threadIdx.x;
    int z = blockIdx.y;
    const float* W  = (z == 0) ? w0 : (z == 1) ? w1 : w2;
    const float* bb = (z == 0) ? b0 : (z == 1) ? b1 : b2;
    const float* c = cab + z * Cdim;
    float acc = bb[i];
    for (int k = 0; k < Cdim; k++) acc += c[k] * W[(size_t)k * Cdim + i];
    beff[z * Cdim + i] = acc;
}

// ====================== HMMA bf16x3 GEMM (batched over z) ==================
// C = alpha_z * (A @ B^T + bias); 3-stage cp.async pipeline, 1 sync/chunk.
#define HG_STAGE 65536
#define HG_SMEM  (3 * HG_STAGE)

__device__ __forceinline__ void hg_load_stage(
    uint32_t sbase, int buf,
    const __nv_bfloat16* __restrict__ a_hi, const __nv_bfloat16* __restrict__ a_lo,
    size_t m0, int lda,
    const __nv_bfloat16* __restrict__ b_hi, const __nv_bfloat16* __restrict__ b_lo,
    size_t n0, int ldb, int k0, int tid)
{
    uint32_t sAh = sbase + buf * HG_STAGE;
    uint32_t sAl = sAh + 16384;
    uint32_t sBh = sAh + 32768;
    uint32_t sBl = sAh + 49152;
#pragma unroll
    for (int t = 0; t < 4; t++) {
        int i = tid + t * 256;
        int row = i >> 3, u = i & 7;
        uint32_t soff = SWZ(row * 128 + u * 16);
        size_t ga = (m0 + row) * (size_t)lda + k0 + u * 8;
        size_t gb = (n0 + row) * (size_t)ldb + k0 + u * 8;
        cpa16(sAh + soff, a_hi + ga);
        cpa16(sAl + soff, a_lo + ga);
        cpa16(sBh + soff, b_hi + gb);
        cpa16(sBl + soff, b_lo + gb);
    }
}

__global__ __launch_bounds__(256, 1) void hmma_gemm(
    const __nv_bfloat16* __restrict__ a_hi, const __nv_bfloat16* __restrict__ a_lo, int lda,
    const __nv_bfloat16* __restrict__ b_hi, const __nv_bfloat16* __restrict__ b_lo, int ldb,
    const float* __restrict__ bias,
    float* __restrict__ outf,
    __nv_bfloat16* __restrict__ out_hi, __nv_bfloat16* __restrict__ out_lo,
    int ldc, int K, float alpha, float alpha2, int mode,
    int az, int bz, int biasz, int cz)
{
    const int z = blockIdx.z;
    a_hi += (size_t)z * az;  a_lo += (size_t)z * az;
    b_hi += (size_t)z * bz;  b_lo += (size_t)z * bz;
    bias += (size_t)z * biasz;
    if (outf)  outf  += (size_t)z * cz;
    if (out_hi) { out_hi += (size_t)z * cz; out_lo += (size_t)z * cz; }
    const float alf = (z == 0) ? alpha : alpha2;

    extern __shared__ char sm[];
    const uint32_t sbase = smem_to_u32(sm);
    const int tid  = threadIdx.x;
    const int warp = tid >> 5, lane = tid & 31;
    const int wm0 = (warp >> 2) * 64;
    const int wn0 = (warp & 3) * 32;
    const size_t m0 = (size_t)blockIdx.y * 128;
    const size_t n0 = (size_t)blockIdx.x * 128;
    const int NC = K >> 6;   // always >= 2 here (K=1024)

    float acc[4][4][4];
#pragma unroll
    for (int i = 0; i < 4; i++)
#pragma unroll
        for (int j = 0; j < 4; j++)
#pragma unroll
            for (int r = 0; r < 4; r++) acc[i][j][r] = 0.f;

    hg_load_stage(sbase, 0, a_hi, a_lo, m0, lda, b_hi, b_lo, n0, ldb, 0, tid);
    CPA_COMMIT();
    hg_load_stage(sbase, 1, a_hi, a_lo, m0, lda, b_hi, b_lo, n0, ldb, 64, tid);
    CPA_COMMIT();

    const int g = lane >> 3;
    const int l7 = lane & 7;

    for (int c = 0; c < NC; ++c) {
        if (c + 1 < NC) { CPA_WAIT1(); } else { CPA_WAIT0(); }
        __syncthreads();
        if (c + 2 < NC) {
            hg_load_stage(sbase, (c + 2) % 3, a_hi, a_lo, m0, lda,
                          b_hi, b_lo, n0, ldb, (c + 2) * 64, tid);
            CPA_COMMIT();
        }
        uint32_t sAh = sbase + (c % 3) * HG_STAGE;
        uint32_t sAl = sAh + 16384;
        uint32_t sBh = sAh + 32768;
        uint32_t sBl = sAh + 49152;

#pragma unroll
        for (int ks = 0; ks < 4; ks++) {
            uint32_t ah[4][4], al[4][4];
            {
                int arow = wm0 + (g & 1) * 8 + l7;
                int akb  = ks * 32 + ((g >> 1) & 1) * 16;
#pragma unroll
                for (int mt = 0; mt < 4; mt++) {
                    uint32_t off = SWZ((arow + mt * 16) * 128 + akb);
                    ldm_x4(ah[mt], sAh + off);
                    ldm_x4(al[mt], sAl + off);
                }
            }
            uint32_t bh[4][2], bl[4][2];
            {
                int nrow = wn0 + ((g >> 1) & 1) * 8 + l7;
                int bkb  = ks * 32 + (g & 1) * 16;
#pragma unroll
                for (int nt = 0; nt < 2; nt++) {
                    uint32_t off = SWZ((nrow + nt * 16) * 128 + bkb);
                    uint32_t r[4];
                    ldm_x4(r, sBh + off);
                    bh[nt * 2 + 0][0] = r[0]; bh[nt * 2 + 0][1] = r[1];
                    bh[nt * 2 + 1][0] = r[2]; bh[nt * 2 + 1][1] = r[3];
                    ldm_x4(r, sBl + off);
                    bl[nt * 2 + 0][0] = r[0]; bl[nt * 2 + 0][1] = r[1];
                    bl[nt * 2 + 1][0] = r[2]; bl[nt * 2 + 1][1] = r[3];
                }
            }
#pragma unroll
            for (int mt = 0; mt < 4; mt++)
#pragma unroll
                for (int j = 0; j < 4; j++) {
                    mma16816(acc[mt][j], ah[mt], bh[j]);
                    mma16816(acc[mt][j], ah[mt], bl[j]);
                    mma16816(acc[mt][j], al[mt], bh[j]);
                }
        }
    }

    const int qrow = lane >> 2;
    const int qcol = (lane & 3) * 2;
#pragma unroll
    for (int j = 0; j < 4; j++) {
        size_t col = n0 + wn0 + j * 8 + qcol;
        float b0 = bias[col], b1 = bias[col + 1];
#pragma unroll
        for (int mt = 0; mt < 4; mt++) {
            size_t row0 = m0 + wm0 + mt * 16 + qrow;
            size_t row1 = row0 + 8;
            float v00 = alf * (acc[mt][j][0] + b0);
            float v01 = alf * (acc[mt][j][1] + b1);
            float v10 = alf * (acc[mt][j][2] + b0);
            float v11 = alf * (acc[mt][j][3] + b1);
            if (mode == 0) {
                float2 r0 = {v00, v01}, r1 = {v10, v11};
                *(float2*)(outf + row0 * ldc + col) = r0;
                *(float2*)(outf + row1 * ldc + col) = r1;
            } else {
                __nv_bfloat162 hh0, ll0, hh1, ll1;
                hh0.x = __float2bfloat16(v00); hh0.y = __float2bfloat16(v01);
                ll0.x = __float2bfloat16(v00 - __bfloat162float(hh0.x));
                ll0.y = __float2bfloat16(v01 - __bfloat162float(hh0.y));
                hh1.x = __float2bfloat16(v10); hh1.y = __float2bfloat16(v11);
                ll1.x = __float2bfloat16(v10 - __bfloat162float(hh1.x));
                ll1.y = __float2bfloat16(v11 - __bfloat162float(hh1.y));
                *(uint32_t*)((char*)out_hi + (row0 * ldc + col) * 2) = *(uint32_t*)&hh0;
                *(uint32_t*)((char*)out_lo + (row0 * ldc + col) * 2) = *(uint32_t*)&ll0;
                *(uint32_t*)((char*)out_hi + (row1 * ldc + col) * 2) = *(uint32_t*)&hh1;
                *(uint32_t*)((char*)out_lo + (row1 * ldc + col) * 2) = *(uint32_t*)&ll1;
            }
        }
    }
}

// ================= HMMA dilated attention (all 3 branches, one launch) =====
#define FA_SMEM 98304

__global__ __launch_bounds__(256) void attn_hmma_all(
    const __nv_bfloat16* __restrict__ qh_g, const __nv_bfloat16* __restrict__ ql_g,
    const __nv_bfloat16* __restrict__ kh_g, const __nv_bfloat16* __restrict__ kl_g,
    const __nv_bfloat16* __restrict__ vh_g, const __nv_bfloat16* __restrict__ vl_g,
    float* __restrict__ O1, float* __restrict__ O2, float* __restrict__ O3,
    float* __restrict__ L1, float* __restrict__ L2, float* __restrict__ L3)
{
    extern __shared__ char sm[];
    const uint32_t sbase = smem_to_u32(sm);
    const uint32_t sQh = sbase, sQl = sbase + 16384;

    // decode branch: bx<32 -> (W=512,R=1); <48 -> (1024,2); else (2048,4)
    int bx = blockIdx.x;
    int W, R;
    float *Obuf, *Lbuf;
    if (bx < 32)      { W = 512;  R = 1; Obuf = O1; Lbuf = L1; }
    else if (bx < 48) { W = 1024; R = 2; Obuf = O2; Lbuf = L2; bx -= 32; }
    else              { W = 2048; R = 4; Obuf = O3; Lbuf = L3; bx -= 48; }
    const int seg = bx >> 2;
    const int qt  = bx & 3;

    const int b   = blockIdx.z;
    const int h   = blockIdx.y;
    const int tid = threadIdx.x;
    const int warp = tid >> 5, lane = tid & 31;
    const int g = lane >> 3, l7 = lane & 7;
    const int segbase = seg * W + (h & (R - 1));
    const int qBase = qt * 128;
    const size_t hoff = (size_t)h * Ddim;

#pragma unroll
    for (int t = 0; t < 4; t++) {
        int i = tid + t * 256;
        int row = i >> 3, u = i & 7;
        int tp = segbase + (qBase + row) * R;
        size_t gidx = (size_t)(b * Tdim + tp) * Cdim + hoff + u * 8;
        uint32_t off = SWZ(row * 128 + u * 16);
        cpa16(sQh + off, qh_g + gidx);
        cpa16(sQl + off, ql_g + gidx);
    }
    {
        uint32_t st = sbase + 32768;
#pragma unroll
        for (int t = 0; t < 2; t++) {
            int i = tid + t * 256;
            int row = i >> 3, u = i & 7;
            int tp = segbase + row * R;
            size_t gidx = (size_t)(b * Tdim + tp) * Cdim + hoff + u * 8;
            uint32_t off = SWZ(row * 128 + u * 16);
            cpa16(st +         off, kh_g + gidx);
            cpa16(st +  8192 + off, kl_g + gidx);
            cpa16(st + 16384 + off, vh_g + gidx);
            cpa16(st + 24576 + off, vl_g + gidx);
        }
    }
    CPA_COMMIT();

    uint32_t qfh[4][4], qfl[4][4];
    float oa[8][4];
#pragma unroll
    for (int nt = 0; nt < 8; nt++)
#pragma unroll
        for (int r = 0; r < 4; r++) oa[nt][r] = 0.f;
    float m0 = -1e30f, m1 = -1e30f, l0 = 0.f, l1 = 0.f;

    const int r0 = lane >> 2;
    const int row0 = qBase + warp * 16 + r0;
    const int row1 = row0 + 8;
    const int colb = (lane & 3) * 2;

    const int ntiles = qt * 2 + 2;
    for (int jt = 0; jt < ntiles; jt++) {
        const int j0 = jt * 64;
        CPA_WAIT0();
        __syncthreads();
        if (jt == 0) {
            int arow = warp * 16 + (g & 1) * 8 + l7;
#pragma unroll
            for (int ks = 0; ks < 4; ks++) {
                int akb = ks * 32 + ((g >> 1) & 1) * 16;
                uint32_t off = SWZ(arow * 128 + akb);
                ldm_x4(qfh[ks], sQh + off);
                ldm_x4(qfl[ks], sQl + off);
            }
        }
        if (jt + 1 < ntiles) {
            uint32_t st = sbase + 32768 + ((jt + 1) & 1) * 32768;
            int jn0 = (jt + 1) * 64;
#pragma unroll
            for (int t = 0; t < 2; t++) {
                int i = tid + t * 256;
                int row = i >> 3, u = i & 7;
                int tp = segbase + (jn0 + row) * R;
                size_t gidx = (size_t)(b * Tdim + tp) * Cdim + hoff + u * 8;
                uint32_t off = SWZ(row * 128 + u * 16);
                cpa16(st +         off, kh_g + gidx);
                cpa16(st +  8192 + off, kl_g + gidx);
                cpa16(st + 16384 + off, vh_g + gidx);
                cpa16(st + 24576 + off, vl_g + gidx);
            }
            CPA_COMMIT();
        }

        uint32_t sKh = sbase + 32768 + (jt & 1) * 32768;
        uint32_t sKl = sKh + 8192;
        uint32_t sVh = sKh + 16384;
        uint32_t sVl = sKh + 24576;

        float sa[8][4];
#pragma unroll
        for (int j = 0; j < 8; j++)
#pragma unroll
            for (int r = 0; r < 4; r++) sa[j][r] = 0.f;

#pragma unroll
        for (int ks = 0; ks < 4; ks++) {
            uint32_t kfh[8][2], kfl[8][2];
            int nrow = ((g >> 1) & 1) * 8 + l7;
            int bkb  = ks * 32 + (g & 1) * 16;
#pragma unroll
            for (int nt16 = 0; nt16 < 4; nt16++) {
                uint32_t off = SWZ((nrow + nt16 * 16) * 128 + bkb);
                uint32_t r[4];
                ldm_x4(r, sKh + off);
                kfh[nt16 * 2 + 0][0] = r[0]; kfh[nt16 * 2 + 0][1] = r[1];
                kfh[nt16 * 2 + 1][0] = r[2]; kfh[nt16 * 2 + 1][1] = r[3];
                ldm_x4(r, sKl + off);
                kfl[nt16 * 2 + 0][0] = r[0]; kfl[nt16 * 2 + 0][1] = r[1];
                kfl[nt16 * 2 + 1][0] = r[2]; kfl[nt16 * 2 + 1][1] = r[3];
            }
#pragma unroll
            for (int j = 0; j < 8; j++) {
                mma16816(sa[j], qfh[ks], kfh[j]);
                mma16816(sa[j], qfh[ks], kfl[j]);
                mma16816(sa[j], qfl[ks], kfh[j]);
            }
        }

        if (jt >= 2 * qt) {
#pragma unroll
            for (int j = 0; j < 8; j++) {
                int key = j0 + j * 8 + colb;
                if (key     > row0) sa[j][0] = -1e30f;
                if (key + 1 > row0) sa[j][1] = -1e30f;
                if (key     > row1) sa[j][2] = -1e30f;
                if (key + 1 > row1) sa[j][3] = -1e30f;
            }
        }

        float rm0 = sa[0][0], rm1 = sa[0][2];
#pragma unroll
        for (int j = 0; j < 8; j++) {
            rm0 = fmaxf(rm0, fmaxf(sa[j][0], sa[j][1]));
            rm1 = fmaxf(rm1, fmaxf(sa[j][2], sa[j][3]));
        }
        rm0 = fmaxf(rm0, __shfl_xor_sync(0xffffffffu, rm0, 1));
        rm0 = fmaxf(rm0, __shfl_xor_sync(0xffffffffu, rm0, 2));
        rm1 = fmaxf(rm1, __shfl_xor_sync(0xffffffffu, rm1, 1));
        rm1 = fmaxf(rm1, __shfl_xor_sync(0xffffffffu, rm1, 2));
        float mn0 = fmaxf(m0, rm0), mn1 = fmaxf(m1, rm1);
        float sc0 = ex2f(m0 - mn0), sc1 = ex2f(m1 - mn1);
        float rs0 = 0.f, rs1 = 0.f;
#pragma unroll
        for (int j = 0; j < 8; j++) {
            sa[j][0] = ex2f(sa[j][0] - mn0);
            sa[j][1] = ex2f(sa[j][1] - mn0);
            sa[j][2] = ex2f(sa[j][2] - mn1);
            sa[j][3] = ex2f(sa[j][3] - mn1);
            rs0 += sa[j][0] + sa[j][1];
            rs1 += sa[j][2] + sa[j][3];
        }
        rs0 += __shfl_xor_sync(0xffffffffu, rs0, 1);
        rs0 += __shfl_xor_sync(0xffffffffu, rs0, 2);
        rs1 += __shfl_xor_sync(0xffffffffu, rs1, 1);
        rs1 += __shfl_xor_sync(0xffffffffu, rs1, 2);
        l0 = l0 * sc0 + rs0; l1 = l1 * sc1 + rs1;
        m0 = mn0; m1 = mn1;
#pragma unroll
        for (int nt = 0; nt < 8; nt++) {
            oa[nt][0] *= sc0; oa[nt][1] *= sc0;
            oa[nt][2] *= sc1; oa[nt][3] *= sc1;
        }

#pragma unroll
        for (int kc = 0; kc < 4; kc++) {
            uint32_t ah[4], al[4];
#pragma unroll
            for (int half = 0; half < 2; half++) {
                const float* p0 = sa[kc * 2 + half];
                __nv_bfloat162 h01, h23, lo01, lo23;
                h01.x = __float2bfloat16(p0[0]); h01.y = __float2bfloat16(p0[1]);
                h23.x = __float2bfloat16(p0[2]); h23.y = __float2bfloat16(p0[3]);
                lo01.x = __float2bfloat16(p0[0] - __bfloat162float(h01.x));
                lo01.y = __float2bfloat16(p0[1] - __bfloat162float(h01.y));
                lo23.x = __float2bfloat16(p0[2] - __bfloat162float(h23.x));
                lo23.y = __float2bfloat16(p0[3] - __bfloat162float(h23.y));
                ah[half * 2 + 0] = *(uint32_t*)&h01;
                ah[half * 2 + 1] = *(uint32_t*)&h23;
                al[half * 2 + 0] = *(uint32_t*)&lo01;
                al[half * 2 + 1] = *(uint32_t*)&lo23;
            }

            uint32_t vfh[8][2], vfl[8][2];
            int vrow = kc * 16 + (g & 1) * 8 + l7;
            int nhalf = (g >> 1) & 1;
#pragma unroll
            for (int nt16 = 0; nt16 < 4; nt16++) {
                uint32_t off = SWZ(vrow * 128 + nt16 * 32 + nhalf * 16);
                uint32_t r[4];
                ldm_x4t(r, sVh + off);
                vfh[nt16 * 2 + 0][0] = r[0]; vfh[nt16 * 2 + 0][1] = r[1];
                vfh[nt16 * 2 + 1][0] = r[2]; vfh[nt16 * 2 + 1][1] = r[3];
                ldm_x4t(r, sVl + off);
                vfl[nt16 * 2 + 0][0] = r[0]; vfl[nt16 * 2 + 0][1] = r[1];
                vfl[nt16 * 2 + 1][0] = r[2]; vfl[nt16 * 2 + 1][1] = r[3];
            }
#pragma unroll
            for (int nt = 0; nt < 8; nt++) {
                mma16816(oa[nt], ah, vfh[nt]);
                mma16816(oa[nt], al, vfh[nt]);
                mma16816(oa[nt], ah, vfl[nt]);
            }
        }
        __syncthreads();
    }

    float inv0 = 1.f / l0, inv1 = 1.f / l1;
    int tp0 = segbase + row0 * R;
    int tp1 = segbase + row1 * R;
    size_t ob0 = (size_t)(b * Tdim + tp0) * Cdim + hoff;
    size_t ob1 = (size_t)(b * Tdim + tp1) * Cdim + hoff;
#pragma unroll
    for (int nt = 0; nt < 8; nt++) {
        int d = nt * 8 + colb;
        float2 w0 = {oa[nt][0] * inv0, oa[nt][1] * inv0};
        float2 w1 = {oa[nt][2] * inv1, oa[nt][3] * inv1};
        *(float2*)(Obuf + ob0 + d) = w0;
        *(float2*)(Obuf + ob1 + d) = w1;
    }
    if ((lane & 3) == 0) {
        Lbuf[(size_t)(b * Tdim + tp0) * Hdim + h] = m0 * LN2F + logf(l0);
        Lbuf[(size_t)(b * Tdim + tp1) * Hdim + h] = m1 * LN2F + logf(l1);
    }
}

// ---------------- combine branches -> y (bf16 hi/lo split out) -------------
__global__ __launch_bounds__(256) void combine_kernel(
    const float* __restrict__ O1, const float* __restrict__ O2,
    const float* __restrict__ O3, const float* __restrict__ L1,
    const float* __restrict__ L2, const float* __restrict__ L3,
    __nv_bfloat16* __restrict__ Yh, __nv_bfloat16* __restrict__ Yl)
{
    int idx = blockIdx.x * 256 + threadIdx.x;
    int c = idx & (Cdim - 1);
    int bt = idx >> 10;
    int t = bt & (Tdim - 1);
    int h = c >> 6;
    int li = bt * Hdim + h;

    float l1 = L1[li];
    bool p2 = (((t ^ h) & 1) == 0);
    bool p3 = (((t ^ h) & 3) == 0);
    float l2 = p2 ? L2[li] : -1e30f;
    float l3 = p3 ? L3[li] : -1e30f;
    float m = fmaxf(l1, fmaxf(l2, l3));
    float w1 = __expf(l1 - m);
    float w2 = p2 ? __expf(l2 - m) : 0.f;
    float w3 = p3 ? __expf(l3 - m) : 0.f;
    float num = w1 * O1[idx];
    if (p2) num += w2 * O2[idx];
    if (p3) num += w3 * O3[idx];
    float y = num / (w1 + w2 + w3);
    __nv_bfloat16 hh = __float2bfloat16(y);
    Yh[idx] = hh;
    Yl[idx] = __float2bfloat16(y - __bfloat162float(hh));
}

// ---------------- launcher --------------------------------------------------
extern "C" void kernel_launch(void* const* d_in, const int* in_sizes, int n_in,
                              void* d_out, int out_size)
{
    const float* x        = (const float*)d_in[0];
    const float* c_attn_w = (const float*)d_in[1];
    const float* c_attn_b = (const float*)d_in[2];
    const float* q_w      = (const float*)d_in[3];
    const float* q_b      = (const float*)d_in[4];
    const float* k_w      = (const float*)d_in[5];
    const float* k_b      = (const float*)d_in[6];
    const float* v_w      = (const float*)d_in[7];
    const float* v_b      = (const float*)d_in[8];
    const float* o_w      = (const float*)d_in[9];
    const float* o_b      = (const float*)d_in[10];
    float* out = (float*)d_out;

    __nv_bfloat16 *p_xhi, *p_xlo, *p_cwsh, *p_cwsl, *p_wTh, *p_wTl;
    __nv_bfloat16 *p_weffh, *p_weffl, *p_attnh, *p_attnl, *p_yh, *p_yl;
    float *p_beff, *p_zero, *p_o1, *p_o2, *p_o3, *p_l1, *p_l2, *p_l3;
    cudaGetSymbolAddress((void**)&p_xhi, g_xhi);
    cudaGetSymbolAddress((void**)&p_xlo, g_xlo);
    cudaGetSymbolAddress((void**)&p_cwsh, g_cwsh);
    cudaGetSymbolAddress((void**)&p_cwsl, g_cwsl);
    cudaGetSymbolAddress((void**)&p_wTh, g_wTh);
    cudaGetSymbolAddress((void**)&p_wTl, g_wTl);
    cudaGetSymbolAddress((void**)&p_weffh, g_weffh);
    cudaGetSymbolAddress((void**)&p_weffl, g_weffl);
    cudaGetSymbolAddress((void**)&p_beff, g_beff);
    cudaGetSymbolAddress((void**)&p_zero, g_zero);
    cudaGetSymbolAddress((void**)&p_attnh, g_attnh);
    cudaGetSymbolAddress((void**)&p_attnl, g_attnl);
    cudaGetSymbolAddress((void**)&p_yh, g_yh);
    cudaGetSymbolAddress((void**)&p_yl, g_yl);
    cudaGetSymbolAddress((void**)&p_o1, g_o1);
    cudaGetSymbolAddress((void**)&p_o2, g_o2);
    cudaGetSymbolAddress((void**)&p_o3, g_o3);
    cudaGetSymbolAddress((void**)&p_l1, g_l1);
    cudaGetSymbolAddress((void**)&p_l2, g_l2);
    cudaGetSymbolAddress((void**)&p_l3, g_l3);

    __nv_bfloat16* p_owh = p_wTh + 3 * (size_t)WPLANE;
    __nv_bfloat16* p_owl = p_wTl + 3 * (size_t)WPLANE;

    cudaFuncSetAttribute(attn_hmma_all, cudaFuncAttributeMaxDynamicSharedMemorySize, FA_SMEM);
    cudaFuncSetAttribute(hmma_gemm, cudaFuncAttributeMaxDynamicSharedMemorySize, HG_SMEM);

    // ---- conversions (3 launches) ----
    split2_kernel<<<(PLANE + 3 * WPLANE) / 1024, 256>>>(
        x, p_xhi, p_xlo, c_attn_w, p_cwsh, p_cwsl);
    transpose_split4<<<dim3(32, 32, 4), 256>>>(q_w, k_w, v_w, o_w, p_wTh, p_wTl);
    beff_kernel<<<dim3(Cdim / 256, 3), 256>>>(c_attn_b, q_w, k_w, v_w, q_b, k_b, v_b, p_beff);

    // ---- weight combine: W_eff^T[z] = wT[z] @ cw_slice[z]^T (batched z=3) --
    hmma_gemm<<<dim3(Cdim / 128, Cdim / 128, 3), 256, HG_SMEM>>>(
        p_wTh, p_wTl, Cdim, p_cwsh, p_cwsl, 3 * Cdim, p_zero,
        nullptr, p_weffh, p_weffl, Cdim, Cdim, 1.f, 1.f, 1,
        WPLANE, Cdim, 0, WPLANE);

    // ---- fused q/k/v projections: attn[z] = x @ W_eff[z]^T + b_eff[z] ------
    hmma_gemm<<<dim3(Cdim / 128, MROWS / 128, 3), 256, HG_SMEM>>>(
        p_xhi, p_xlo, Cdim, p_weffh, p_weffl, Cdim, p_beff,
        nullptr, p_attnh, p_attnl, Cdim, Cdim, 0.125f * LOG2E, 1.f, 1,
        0, WPLANE, Cdim, PLANE);

    __nv_bfloat16* p_qh = p_attnh + 0 * (size_t)PLANE; __nv_bfloat16* p_ql = p_attnl + 0 * (size_t)PLANE;
    __nv_bfloat16* p_kh = p_attnh + 1 * (size_t)PLANE; __nv_bfloat16* p_kl = p_attnl + 1 * (size_t)PLANE;
    __nv_bfloat16* p_vh = p_attnh + 2 * (size_t)PLANE; __nv_bfloat16* p_vl = p_attnl + 2 * (size_t)PLANE;

    // ---- all three dilated-attention branches in ONE launch ----
    attn_hmma_all<<<dim3(56, Hdim, Bdim), 256, FA_SMEM>>>(
        p_qh, p_ql, p_kh, p_kl, p_vh, p_vl,
        p_o1, p_o2, p_o3, p_l1, p_l2, p_l3);

    // ---- combine -> y (bf16 split) ----
    combine_kernel<<<PLANE / 256, 256>>>(
        p_o1, p_o2, p_o3, p_l1, p_l2, p_l3, p_yh, p_yl);

    // ---- out = y @ o_w + o_b (fp32) ----
    hmma_gemm<<<dim3(Cdim / 128, MROWS / 128, 1), 256, HG_SMEM>>>(
        p_yh, p_yl, Cdim, p_owh, p_owl, Cdim, o_b,
        out, nullptr, nullptr, Cdim, Cdim, 1.f, 1.f, 0,
        0, 0, 0, 0);
}